// round 4
// baseline (speedup 1.0000x reference)
#include <cuda_runtime.h>

// Problem constants (fixed shapes)
#define N_MAX 50000
#define M_MAX 800000
#define D 96          // K*FAC
#define KCAP 8
#define FAC 12

#define CAP 18                    // cached neighbors per node (fp32 rows)
#define NSTRIDE (CAP * 384 + 32)  // 6944 B per node slab
#define ROUTE_SMEM (16 * NSTRIDE) // 111104 B per 128-thread block (16 nodes)

typedef unsigned long long u64;

// Static scratch (no allocations allowed)
__device__ float g_za[N_MAX * D];   // z double-buffer A (fp32)
__device__ float g_zb[N_MAX * D];   // z double-buffer B (fp32)
__device__ float g_c[N_MAX * D];    // init-layer output (pre-norm)
__device__ float g_wt[D * 256];     // W transposed to [out=96][in=256]
__device__ int   g_deg[N_MAX];
__device__ int   g_rowptr[N_MAX + 1];
__device__ int   g_cursor[N_MAX];
__device__ int   g_colsrc[M_MAX];
__device__ int   g_dhist[64];
__device__ int   g_dcur[64];
__device__ int   g_perm[N_MAX];

// ---------------- packed f32x2 helpers (Blackwell FFMA2) -------------------
__device__ __forceinline__ u64 pk2(float lo, float hi) {
    u64 r; asm("mov.b64 %0,{%1,%2};" : "=l"(r) : "f"(lo), "f"(hi)); return r;
}
__device__ __forceinline__ float2 upk2(u64 v) {
    float2 f; asm("mov.b64 {%0,%1},%2;" : "=f"(f.x), "=f"(f.y) : "l"(v)); return f;
}
__device__ __forceinline__ u64 fma2_(u64 a, u64 b, u64 c) {
    u64 d; asm("fma.rn.f32x2 %0,%1,%2,%3;" : "=l"(d) : "l"(a), "l"(b), "l"(c)); return d;
}
__device__ __forceinline__ u64 mul2_(u64 a, u64 b) {
    u64 d; asm("mul.rn.f32x2 %0,%1,%2;" : "=l"(d) : "l"(a), "l"(b)); return d;
}
__device__ __forceinline__ u64 add2_(u64 a, u64 b) {
    u64 d; asm("add.rn.f32x2 %0,%1,%2;" : "=l"(d) : "l"(a), "l"(b)); return d;
}

// ---------------------------------------------------------------------------
// zero + W transpose fused. W_init [K,256,FAC] -> g_wt [96][256]
__global__ void zero_wt_kernel(const float* __restrict__ W, int n) {
    int i = blockIdx.x * blockDim.x + threadIdx.x;
    if (i < n) g_deg[i] = 0;
    if (i < 64) g_dhist[i] = 0;
    if (i < D * 256) {
        int o = i >> 8, c = i & 255;
        int k = o / FAC, oo = o % FAC;
        g_wt[i] = W[k * (256 * FAC) + c * FAC + oo];
    }
}

// ---------------------------------------------------------------------------
// Init layer: g_c[n][o] = relu( X[n,:] . Wt[o,:] + b[o] )   (f32x2 FMAs)
__global__ void __launch_bounds__(96) init_gemm(const float* __restrict__ X,
                                                const float* __restrict__ bv, int n) {
    __shared__ float xs[32][256];
    int t = threadIdx.x;
    int nb = blockIdx.x * 32;
    for (int j = t; j < 32 * 256; j += 96) {
        int q = j >> 8;
        xs[q][j & 255] = (nb + q < n) ? X[nb * 256 + j] : 0.f;
    }
    __syncthreads();

    u64 acc[32];
#pragma unroll
    for (int q = 0; q < 32; q++) acc[q] = 0ull;

    const float4* wrow = (const float4*)(g_wt + t * 256);
#pragma unroll 2
    for (int i4 = 0; i4 < 64; i4++) {
        float4 w = wrow[i4];
        u64 w0 = pk2(w.x, w.y), w1 = pk2(w.z, w.w);
#pragma unroll
        for (int q = 0; q < 32; q++) {
            float4 xv = *(const float4*)&xs[q][i4 * 4];
            acc[q] = fma2_(w0, pk2(xv.x, xv.y), acc[q]);
            acc[q] = fma2_(w1, pk2(xv.z, xv.w), acc[q]);
        }
    }
    float bb = bv[t];
    int cnt = min(32, n - nb);
    for (int q = 0; q < cnt; q++) {
        float2 h = upk2(acc[q]);
        g_c[(nb + q) * D + t] = fmaxf(h.x + h.y + bb, 0.f);
    }
}

// ---------------------------------------------------------------------------
// CSR build
__global__ void hist_kernel(const int* __restrict__ edges, int m) {
    int e = blockIdx.x * blockDim.x + threadIdx.x;
    if (e < m) atomicAdd(&g_deg[edges[m + e]], 1);
}

__global__ void scan_kernel(int n) {
    __shared__ int wsum[32];
    int t = threadIdx.x, lane = t & 31, wid = t >> 5;
    int running = 0;
    for (int base = 0; base < n; base += 1024) {
        int idx = base + t;
        int v = (idx < n) ? g_deg[idx] : 0;
        int x = v;
#pragma unroll
        for (int off = 1; off < 32; off <<= 1) {
            int y = __shfl_up_sync(0xffffffffu, x, off);
            if (lane >= off) x += y;
        }
        if (lane == 31) wsum[wid] = x;
        __syncthreads();
        if (wid == 0) {
            int w = wsum[lane];
#pragma unroll
            for (int off = 1; off < 32; off <<= 1) {
                int y = __shfl_up_sync(0xffffffffu, w, off);
                if (lane >= off) w += y;
            }
            wsum[lane] = w;
        }
        __syncthreads();
        int pre = (wid > 0) ? wsum[wid - 1] : 0;
        int excl = running + pre + x - v;
        if (idx < n) { g_rowptr[idx] = excl; g_cursor[idx] = excl; }
        int total = wsum[31];
        __syncthreads();
        running += total;
    }
    if (t == 0) g_rowptr[n] = running;
}

__global__ void scatter_kernel(const int* __restrict__ edges, int m) {
    int e = blockIdx.x * blockDim.x + threadIdx.x;
    if (e < m) {
        int d = edges[m + e];
        int pos = atomicAdd(&g_cursor[d], 1);
        g_colsrc[pos] = edges[e];
    }
}

// Sort each row's src list: deterministic accumulation order.
__global__ void sort_rows(int n) {
    int node = blockIdx.x * blockDim.x + threadIdx.x;
    if (node >= n) return;
    int s = g_rowptr[node], e = g_rowptr[node + 1];
    for (int i = s + 1; i < e; i++) {
        int v = g_colsrc[i];
        int j = i - 1;
        while (j >= s && g_colsrc[j] > v) { g_colsrc[j + 1] = g_colsrc[j]; j--; }
        g_colsrc[j + 1] = v;
    }
}

// ---------------------------------------------------------------------------
// Degree-balanced permutation (bucket by clamped degree), smem-local hist.
__global__ void dhist_kernel(int n) {
    __shared__ int h[64];
    if (threadIdx.x < 64) h[threadIdx.x] = 0;
    __syncthreads();
    int i = blockIdx.x * blockDim.x + threadIdx.x;
    if (i < n) atomicAdd(&h[min(g_deg[i], 63)], 1);
    __syncthreads();
    if (threadIdx.x < 64 && h[threadIdx.x]) atomicAdd(&g_dhist[threadIdx.x], h[threadIdx.x]);
}

__global__ void dscan_kernel() {
    if (threadIdx.x == 0) {
        int run = 0;
        for (int i = 0; i < 64; i++) { g_dcur[i] = run; run += g_dhist[i]; }
    }
}

__global__ void dscatter_kernel(int n) {
    int i = blockIdx.x * blockDim.x + threadIdx.x;
    if (i < n) {
        int pos = atomicAdd(&g_dcur[min(g_deg[i], 63)], 1);
        g_perm[pos] = i;
    }
}

// ---------------------------------------------------------------------------
// One-time prep after init: g_za = l2norm(relu(g_c)) per capsule.
__global__ void prep_kernel(int n) {
    int idx = blockIdx.x * blockDim.x + threadIdx.x;
    if (idx >= n * KCAP) return;
    const float4* cp = (const float4*)(g_c + idx * FAC);
    float4 a0 = cp[0], a1 = cp[1], a2 = cp[2];
    float t[12] = {a0.x, a0.y, a0.z, a0.w, a1.x, a1.y, a1.z, a1.w,
                   a2.x, a2.y, a2.z, a2.w};
    float s = 0.f;
#pragma unroll
    for (int i = 0; i < 12; i++) { t[i] = fmaxf(t[i], 0.f); s += t[i] * t[i]; }
    float rn = rsqrtf(s + 1e-12f);
    float4* zp = (float4*)(g_za + idx * FAC);
    zp[0] = make_float4(t[0]*rn, t[1]*rn, t[2]*rn, t[3]*rn);
    zp[1] = make_float4(t[4]*rn, t[5]*rn, t[6]*rn, t[7]*rn);
    zp[2] = make_float4(t[8]*rn, t[9]*rn, t[10]*rn, t[11]*rn);
}

// ---------------------------------------------------------------------------
// Load one capsule slice (48B) as 6 packed f32x2 regs.
__device__ __forceinline__ void ld_slice(const float4* p, u64* f) {
    float4 v0 = p[0], v1 = p[1], v2 = p[2];
    f[0] = pk2(v0.x, v0.y); f[1] = pk2(v0.z, v0.w);
    f[2] = pk2(v1.x, v1.y); f[3] = pk2(v1.z, v1.w);
    f[4] = pk2(v2.x, v2.y); f[5] = pk2(v2.z, v2.w);
}

__device__ __forceinline__ float dot12(const u64* f, const u64* c) {
    u64 t0 = mul2_(f[0], c[0]);
    u64 t1 = mul2_(f[1], c[1]);
    t0 = fma2_(f[2], c[2], t0);
    t1 = fma2_(f[3], c[3], t1);
    t0 = fma2_(f[4], c[4], t0);
    t1 = fma2_(f[5], c[5], t1);
    float2 h = upk2(add2_(t0, t1));
    return h.x + h.y;
}

// Fused routing layer: gather neighbor z (fp32) to smem once, run all 6
// iterations with c in registers. 8 lanes per node (lane = capsule),
// 4 nodes/warp, 16 nodes per 128-thread block, 2 blocks/SM.
// mode 0: write z_next = l2norm(relu(c)) to zout.
// mode 1: write relu(c) to zout (final output).
__global__ void __launch_bounds__(128) routing_layer(const float* __restrict__ zin,
                                                     float* __restrict__ zout,
                                                     int n, int mode) {
    extern __shared__ char sm[];
    int lane = threadIdx.x & 31;
    int warp = threadIdx.x >> 5;
    int group = lane >> 3;
    int cap = lane & 7;
    unsigned mask = 0xFFu << (group << 3);
    int local = warp * 4 + group;
    int slot = blockIdx.x * 16 + local;
    bool valid = slot < n;
    int node = valid ? g_perm[slot] : 0;

    int s = 0, deg = 0;
    if (valid) { s = g_rowptr[node]; deg = g_rowptr[node + 1] - s; }
    int cached = min(deg, CAP);

    char* slab = sm + local * NSTRIDE;

    // ---- fill: gather cached neighbor z rows (fp32, 384B each) ----
#pragma unroll 2
    for (int e = 0; e < cached; e++) {
        int src = g_colsrc[s + e];
        const uint4* gp = (const uint4*)(zin + (size_t)src * D);
        uint4* row = (uint4*)(slab + e * 384);
        row[cap]      = gp[cap];
        row[cap + 8]  = gp[cap + 8];
        row[cap + 16] = gp[cap + 16];
    }

    // ---- self z (packed) ----
    u64 z2[6], c2[6];
    if (valid) {
        ld_slice((const float4*)(zin + (size_t)node * D + cap * FAC), z2);
#pragma unroll
        for (int i = 0; i < 6; i++) c2[i] = z2[i];
    }
    __syncwarp();

    // ---- 6 routing iterations from smem / registers ----
    for (int it = 0; it < 6; it++) {
        u64 acc[6];
#pragma unroll
        for (int i = 0; i < 6; i++) acc[i] = 0ull;

        int e = 0;
        for (; e + 1 < cached; e += 2) {
            u64 fA[6], fB[6];
            ld_slice((const float4*)(slab + e * 384 + cap * 48), fA);
            ld_slice((const float4*)(slab + (e + 1) * 384 + cap * 48), fB);
            float attA = dot12(fA, c2);
            float attB = dot12(fB, c2);
            // z,c unit vectors -> att in [-1,1]: exp safe without max-sub
            float exA = __expf(attA), exB = __expf(attB);
            float sA = exA, sB = exB;
            sA += __shfl_xor_sync(mask, sA, 1); sB += __shfl_xor_sync(mask, sB, 1);
            sA += __shfl_xor_sync(mask, sA, 2); sB += __shfl_xor_sync(mask, sB, 2);
            sA += __shfl_xor_sync(mask, sA, 4); sB += __shfl_xor_sync(mask, sB, 4);
            u64 pA = pk2(__fdividef(exA, sA), __fdividef(exA, sA));
            u64 pB = pk2(__fdividef(exB, sB), __fdividef(exB, sB));
#pragma unroll
            for (int i = 0; i < 6; i++) acc[i] = fma2_(pA, fA[i], acc[i]);
#pragma unroll
            for (int i = 0; i < 6; i++) acc[i] = fma2_(pB, fB[i], acc[i]);
        }
        if (e < cached) {
            u64 fA[6];
            ld_slice((const float4*)(slab + e * 384 + cap * 48), fA);
            float att = dot12(fA, c2);
            float ex = __expf(att);
            float sm_ = ex;
            sm_ += __shfl_xor_sync(mask, sm_, 1);
            sm_ += __shfl_xor_sync(mask, sm_, 2);
            sm_ += __shfl_xor_sync(mask, sm_, 4);
            float p = __fdividef(ex, sm_);
            u64 p2 = pk2(p, p);
#pragma unroll
            for (int i = 0; i < 6; i++) acc[i] = fma2_(p2, fA[i], acc[i]);
        }
        // overflow edges streamed from L2, order-preserving
        for (int e2 = cached; e2 < deg; e2++) {
            u64 fA[6];
            ld_slice((const float4*)(zin + (size_t)g_colsrc[s + e2] * D + cap * FAC), fA);
            float att = dot12(fA, c2);
            float ex = __expf(att);
            float sm_ = ex;
            sm_ += __shfl_xor_sync(mask, sm_, 1);
            sm_ += __shfl_xor_sync(mask, sm_, 2);
            sm_ += __shfl_xor_sync(mask, sm_, 4);
            float p = __fdividef(ex, sm_);
            u64 p2 = pk2(p, p);
#pragma unroll
            for (int i = 0; i < 6; i++) acc[i] = fma2_(p2, fA[i], acc[i]);
        }

        // c = l2norm(z + acc)
        u64 v2[6];
        float ss = 0.f;
#pragma unroll
        for (int i = 0; i < 6; i++) {
            v2[i] = add2_(z2[i], acc[i]);
            float2 h = upk2(v2[i]);
            ss += h.x * h.x + h.y * h.y;
        }
        float rn = rsqrtf(ss + 1e-12f);
        u64 rn2 = pk2(rn, rn);
#pragma unroll
        for (int i = 0; i < 6; i++) c2[i] = mul2_(v2[i], rn2);
    }

    if (valid) {
        float c[12];
#pragma unroll
        for (int i = 0; i < 6; i++) {
            float2 h = upk2(c2[i]);
            c[2 * i] = fmaxf(h.x, 0.f);
            c[2 * i + 1] = fmaxf(h.y, 0.f);
        }
        if (mode == 0) {
            // next layer's z = l2norm(relu(c))
            float ss = 0.f;
#pragma unroll
            for (int i = 0; i < 12; i++) ss += c[i] * c[i];
            float rn = rsqrtf(ss + 1e-12f);
#pragma unroll
            for (int i = 0; i < 12; i++) c[i] *= rn;
        }
        float4* co = (float4*)(zout + (size_t)node * D + cap * FAC);
        co[0] = make_float4(c[0], c[1], c[2], c[3]);
        co[1] = make_float4(c[4], c[5], c[6], c[7]);
        co[2] = make_float4(c[8], c[9], c[10], c[11]);
    }
}

// ---------------------------------------------------------------------------
extern "C" void kernel_launch(void* const* d_in, const int* in_sizes, int n_in,
                              void* d_out, int out_size) {
    const float* X     = (const float*)d_in[0];
    const int*   edges = (const int*)d_in[1];
    const float* W     = (const float*)d_in[2];
    const float* b     = (const float*)d_in[3];
    int n = in_sizes[0] / 256;   // 50000
    int m = in_sizes[1] / 2;     // 800000

    cudaFuncSetAttribute(routing_layer,
                         cudaFuncAttributeMaxDynamicSharedMemorySize, ROUTE_SMEM);

    float* za; cudaGetSymbolAddress((void**)&za, g_za);
    float* zb; cudaGetSymbolAddress((void**)&zb, g_zb);

    // zero + W transpose, then init layer
    zero_wt_kernel<<<(n + 255) / 256, 256>>>(W, n);
    init_gemm<<<(n + 31) / 32, 96>>>(X, b, n);

    // CSR by dst (deterministic: rows sorted by src)
    hist_kernel<<<(m + 255) / 256, 256>>>(edges, m);
    scan_kernel<<<1, 1024>>>(n);
    scatter_kernel<<<(m + 255) / 256, 256>>>(edges, m);
    sort_rows<<<(n + 255) / 256, 256>>>(n);

    // degree-balanced node permutation
    dhist_kernel<<<(n + 255) / 256, 256>>>(n);
    dscan_kernel<<<1, 32>>>();
    dscatter_kernel<<<(n + 255) / 256, 256>>>(n);

    // one-time prep, then 4 fused routing layers (z double-buffered)
    prep_kernel<<<(n * KCAP + 255) / 256, 256>>>(n);
    int blocks = (n + 15) / 16;
    routing_layer<<<blocks, 128, ROUTE_SMEM>>>(za, zb, n, 0);            // L1
    routing_layer<<<blocks, 128, ROUTE_SMEM>>>(zb, za, n, 0);            // L2
    routing_layer<<<blocks, 128, ROUTE_SMEM>>>(za, zb, n, 0);            // L3
    routing_layer<<<blocks, 128, ROUTE_SMEM>>>(zb, (float*)d_out, n, 1); // L4
}

// round 5
// speedup vs baseline: 1.5855x; 1.5855x over previous
#include <cuda_runtime.h>
#include <cuda_fp16.h>

// Problem constants (fixed shapes)
#define N_MAX 50000
#define M_MAX 800000
#define D 96          // K*FAC
#define KCAP 8
#define FAC 12

#define CAP 18                     // cached neighbors per node in smem (fp16)
#define NSTRIDE (CAP * 192 + 32)   // 3488 B per node slab
#define ROUTE_SMEM (16 * NSTRIDE)  // 55808 B per 128-thread block -> 4 blocks/SM

// Static scratch (no allocations allowed)
__device__ __half g_zh_a[N_MAX * D];   // fp16 z double-buffer A (gather source)
__device__ __half g_zh_b[N_MAX * D];   // fp16 z double-buffer B
__device__ float  g_z32_a[N_MAX * D];  // fp32 z double-buffer A (self-term)
__device__ float  g_z32_b[N_MAX * D];  // fp32 z double-buffer B
__device__ float  g_c[N_MAX * D];      // init-layer output (pre-norm)
__device__ float  g_wt[D * 256];       // W transposed to [out=96][in=256]
__device__ int    g_deg[N_MAX];
__device__ int    g_rowptr[N_MAX + 1];
__device__ int    g_cursor[N_MAX];
__device__ int    g_colsrc[M_MAX];
__device__ int    g_bsum[64];
__device__ int    g_boff[64];
__device__ int    g_dhist[64];
__device__ int    g_dcur[64];
__device__ int    g_perm[N_MAX];

// ---------------------------------------------------------------------------
// zero + W transpose fused. W_init [K,256,FAC] -> g_wt [96][256]
__global__ void zero_wt_kernel(const float* __restrict__ W, int n) {
    int i = blockIdx.x * blockDim.x + threadIdx.x;
    if (i < n) g_deg[i] = 0;
    if (i < 64) g_dhist[i] = 0;
    if (i < D * 256) {
        int o = i >> 8, c = i & 255;
        int k = o / FAC, oo = o % FAC;
        g_wt[i] = W[k * (256 * FAC) + c * FAC + oo];
    }
}

// ---------------------------------------------------------------------------
// Init layer: g_c[n][o] = relu( X[n,:] . Wt[o,:] + b[o] )
__global__ void __launch_bounds__(96) init_gemm(const float* __restrict__ X,
                                                const float* __restrict__ bv, int n) {
    __shared__ float xs[32][256];
    int t = threadIdx.x;
    int nb = blockIdx.x * 32;
    for (int j = t; j < 32 * 256; j += 96) {
        int q = j >> 8;
        xs[q][j & 255] = (nb + q < n) ? X[nb * 256 + j] : 0.f;
    }
    __syncthreads();

    float acc[32];
#pragma unroll
    for (int q = 0; q < 32; q++) acc[q] = 0.f;

    const float4* wrow = (const float4*)(g_wt + t * 256);
#pragma unroll 2
    for (int i4 = 0; i4 < 64; i4++) {
        float4 w = wrow[i4];
#pragma unroll
        for (int q = 0; q < 32; q++) {
            float4 xv = *(const float4*)&xs[q][i4 * 4];
            acc[q] += w.x * xv.x + w.y * xv.y + w.z * xv.z + w.w * xv.w;
        }
    }
    float bb = bv[t];
    int cnt = min(32, n - nb);
    for (int q = 0; q < cnt; q++)
        g_c[(nb + q) * D + t] = fmaxf(acc[q] + bb, 0.f);
}

// ---------------------------------------------------------------------------
// CSR build: hist -> 3-phase hierarchical scan -> scatter -> per-row sort
__global__ void hist_kernel(const int* __restrict__ edges, int m) {
    int e = blockIdx.x * blockDim.x + threadIdx.x;
    if (e < m) atomicAdd(&g_deg[edges[m + e]], 1);
}

// phase 1: per-block (1024-wide) exclusive scan of degrees; block total -> g_bsum
__global__ void scan1_kernel(int n) {
    __shared__ int wsum[32];
    int t = threadIdx.x, lane = t & 31, wid = t >> 5;
    int idx = blockIdx.x * 1024 + t;
    int v = (idx < n) ? g_deg[idx] : 0;
    int x = v;
#pragma unroll
    for (int off = 1; off < 32; off <<= 1) {
        int y = __shfl_up_sync(0xffffffffu, x, off);
        if (lane >= off) x += y;
    }
    if (lane == 31) wsum[wid] = x;
    __syncthreads();
    if (wid == 0) {
        int w = wsum[lane];
#pragma unroll
        for (int off = 1; off < 32; off <<= 1) {
            int y = __shfl_up_sync(0xffffffffu, w, off);
            if (lane >= off) w += y;
        }
        wsum[lane] = w;
    }
    __syncthreads();
    int pre = (wid > 0) ? wsum[wid - 1] : 0;
    if (idx < n) g_rowptr[idx] = pre + x - v;   // block-local exclusive
    if (t == 1023) g_bsum[blockIdx.x] = pre + x;
}

// phase 2: exclusive scan of <=64 block totals (single warp pass of 64)
__global__ void scan2_kernel(int nblocks, int n) {
    int t = threadIdx.x;  // 64 threads
    int v = (t < nblocks) ? g_bsum[t] : 0;
    int x = v;
    int lane = t & 31, wid = t >> 5;
    __shared__ int ws[2];
#pragma unroll
    for (int off = 1; off < 32; off <<= 1) {
        int y = __shfl_up_sync(0xffffffffu, x, off);
        if (lane >= off) x += y;
    }
    if (lane == 31) ws[wid] = x;
    __syncthreads();
    int add = (wid == 1) ? ws[0] : 0;
    g_boff[t] = add + x - v;
    if (t == 63) g_rowptr[n] = add + x;
}

// phase 3: add block offsets, set cursor
__global__ void scan3_kernel(int n) {
    int idx = blockIdx.x * blockDim.x + threadIdx.x;
    if (idx < n) {
        int r = g_rowptr[idx] + g_boff[idx >> 10];
        g_rowptr[idx] = r;
        g_cursor[idx] = r;
    }
}

__global__ void scatter_kernel(const int* __restrict__ edges, int m) {
    int e = blockIdx.x * blockDim.x + threadIdx.x;
    if (e < m) {
        int d = edges[m + e];
        int pos = atomicAdd(&g_cursor[d], 1);
        g_colsrc[pos] = edges[e];
    }
}

// Sort each row's src list: deterministic accumulation order.
__global__ void sort_rows(int n) {
    int node = blockIdx.x * blockDim.x + threadIdx.x;
    if (node >= n) return;
    int s = g_rowptr[node], e = g_rowptr[node + 1];
    for (int i = s + 1; i < e; i++) {
        int v = g_colsrc[i];
        int j = i - 1;
        while (j >= s && g_colsrc[j] > v) { g_colsrc[j + 1] = g_colsrc[j]; j--; }
        g_colsrc[j + 1] = v;
    }
}

// ---------------------------------------------------------------------------
// Degree-balanced permutation (bucket by clamped degree), smem-local hist.
__global__ void dhist_kernel(int n) {
    __shared__ int h[64];
    if (threadIdx.x < 64) h[threadIdx.x] = 0;
    __syncthreads();
    int i = blockIdx.x * blockDim.x + threadIdx.x;
    if (i < n) atomicAdd(&h[min(g_deg[i], 63)], 1);
    __syncthreads();
    if (threadIdx.x < 64 && h[threadIdx.x]) atomicAdd(&g_dhist[threadIdx.x], h[threadIdx.x]);
}

__global__ void dscan_kernel() {
    if (threadIdx.x == 0) {
        int run = 0;
        for (int i = 0; i < 64; i++) { g_dcur[i] = run; run += g_dhist[i]; }
    }
}

__global__ void dscatter_kernel(int n) {
    int i = blockIdx.x * blockDim.x + threadIdx.x;
    if (i < n) {
        int pos = atomicAdd(&g_dcur[min(g_deg[i], 63)], 1);
        g_perm[pos] = i;
    }
}

// ---------------------------------------------------------------------------
// One-time prep after init: z_a = l2norm(relu(g_c)) -> fp32 + fp16 buffers.
__global__ void prep_kernel(int n) {
    int idx = blockIdx.x * blockDim.x + threadIdx.x;
    if (idx >= n * KCAP) return;
    const float4* cp = (const float4*)(g_c + idx * FAC);
    float4 a0 = cp[0], a1 = cp[1], a2 = cp[2];
    float t[12] = {a0.x, a0.y, a0.z, a0.w, a1.x, a1.y, a1.z, a1.w,
                   a2.x, a2.y, a2.z, a2.w};
    float s = 0.f;
#pragma unroll
    for (int i = 0; i < 12; i++) { t[i] = fmaxf(t[i], 0.f); s += t[i] * t[i]; }
    float rn = rsqrtf(s + 1e-12f);
#pragma unroll
    for (int i = 0; i < 12; i++) t[i] *= rn;
    float4* zp = (float4*)(g_z32_a + idx * FAC);
    zp[0] = make_float4(t[0], t[1], t[2], t[3]);
    zp[1] = make_float4(t[4], t[5], t[6], t[7]);
    zp[2] = make_float4(t[8], t[9], t[10], t[11]);
    uint2* zh = (uint2*)(g_zh_a + idx * FAC);
    __half2 h0 = __floats2half2_rn(t[0], t[1]);
    __half2 h1 = __floats2half2_rn(t[2], t[3]);
    __half2 h2 = __floats2half2_rn(t[4], t[5]);
    __half2 h3 = __floats2half2_rn(t[6], t[7]);
    __half2 h4 = __floats2half2_rn(t[8], t[9]);
    __half2 h5 = __floats2half2_rn(t[10], t[11]);
    zh[0] = make_uint2(*(unsigned*)&h0, *(unsigned*)&h1);
    zh[1] = make_uint2(*(unsigned*)&h2, *(unsigned*)&h3);
    zh[2] = make_uint2(*(unsigned*)&h4, *(unsigned*)&h5);
}

// ---------------------------------------------------------------------------
__device__ __forceinline__ void cvt12(uint2 a0, uint2 a1, uint2 a2, float* f) {
    float2 t;
    t = __half22float2(*(__half2*)&a0.x); f[0] = t.x;  f[1] = t.y;
    t = __half22float2(*(__half2*)&a0.y); f[2] = t.x;  f[3] = t.y;
    t = __half22float2(*(__half2*)&a1.x); f[4] = t.x;  f[5] = t.y;
    t = __half22float2(*(__half2*)&a1.y); f[6] = t.x;  f[7] = t.y;
    t = __half22float2(*(__half2*)&a2.x); f[8] = t.x;  f[9] = t.y;
    t = __half22float2(*(__half2*)&a2.y); f[10] = t.x; f[11] = t.y;
}

// Fused routing layer: gather neighbor z (fp16) to smem once, run all 6
// iterations with c in registers. 8 lanes per node (lane = capsule),
// 4 nodes/warp, 16 nodes per 128-thread block, 4 blocks/SM.
// mode 0: write z_next = l2norm(relu(c)) to zh_out (fp16) + z32_out (fp32).
// mode 1: write relu(c) to fout (final output).
__global__ void __launch_bounds__(128, 4)
routing_layer(const __half* __restrict__ zh_in, const float* __restrict__ z32_in,
              __half* __restrict__ zh_out, float* __restrict__ z32_out,
              float* __restrict__ fout, int n, int mode) {
    extern __shared__ char sm[];
    int lane = threadIdx.x & 31;
    int warp = threadIdx.x >> 5;
    int group = lane >> 3;
    int cap = lane & 7;
    unsigned mask = 0xFFu << (group << 3);
    int local = warp * 4 + group;
    int slot = blockIdx.x * 16 + local;
    bool valid = slot < n;
    int node = valid ? g_perm[slot] : 0;

    int s = 0, deg = 0;
    if (valid) { s = g_rowptr[node]; deg = g_rowptr[node + 1] - s; }
    int cached = min(deg, CAP);

    char* slab = sm + local * NSTRIDE;

    // ---- fill: gather cached neighbor z rows (fp16, 192B each) ----
    for (int e = 0; e < cached; e++) {
        int src = g_colsrc[s + e];
        const uint4* gp = (const uint4*)(zh_in + (size_t)src * D);
        uint4* row = (uint4*)(slab + e * 192);
        row[cap] = gp[cap];
        if (cap < 4) row[8 + cap] = gp[8 + cap];
    }

    // ---- z_self (fp32); c init = z ----
    float z[12], c[12];
    if (valid) {
        const float4* zb = (const float4*)(z32_in + (size_t)node * D + cap * FAC);
        float4 a0 = zb[0], a1 = zb[1], a2 = zb[2];
        z[0] = a0.x; z[1] = a0.y; z[2]  = a0.z; z[3]  = a0.w;
        z[4] = a1.x; z[5] = a1.y; z[6]  = a1.z; z[7]  = a1.w;
        z[8] = a2.x; z[9] = a2.y; z[10] = a2.z; z[11] = a2.w;
#pragma unroll
        for (int i = 0; i < 12; i++) c[i] = z[i];
    }
    __syncwarp();

    // ---- 6 routing iterations from smem / registers ----
    for (int it = 0; it < 6; it++) {
        float acc[12];
#pragma unroll
        for (int i = 0; i < 12; i++) acc[i] = 0.f;

        int e = 0;
        // 2-edge unrolled: two independent shuffle/exp chains in flight
        for (; e + 1 < cached; e += 2) {
            const uint2* rA = (const uint2*)(slab + e * 192 + cap * 24);
            const uint2* rB = (const uint2*)(slab + (e + 1) * 192 + cap * 24);
            uint2 A0 = rA[0], A1 = rA[1], A2 = rA[2];
            uint2 B0 = rB[0], B1 = rB[1], B2 = rB[2];
            float fA[12], fB[12];
            cvt12(A0, A1, A2, fA);
            cvt12(B0, B1, B2, fB);
            float attA = 0.f, attB = 0.f;
#pragma unroll
            for (int i = 0; i < 12; i++) { attA += fA[i] * c[i]; attB += fB[i] * c[i]; }
            // z,c unit vectors -> att in [-1,1]: exp safe without max-sub
            float exA = __expf(attA), exB = __expf(attB);
            float sA = exA, sB = exB;
            sA += __shfl_xor_sync(mask, sA, 1); sB += __shfl_xor_sync(mask, sB, 1);
            sA += __shfl_xor_sync(mask, sA, 2); sB += __shfl_xor_sync(mask, sB, 2);
            sA += __shfl_xor_sync(mask, sA, 4); sB += __shfl_xor_sync(mask, sB, 4);
            float pA = __fdividef(exA, sA);
            float pB = __fdividef(exB, sB);
#pragma unroll
            for (int i = 0; i < 12; i++) acc[i] += pA * fA[i];
#pragma unroll
            for (int i = 0; i < 12; i++) acc[i] += pB * fB[i];
        }
        if (e < cached) {
            const uint2* rA = (const uint2*)(slab + e * 192 + cap * 24);
            uint2 A0 = rA[0], A1 = rA[1], A2 = rA[2];
            float fA[12];
            cvt12(A0, A1, A2, fA);
            float att = 0.f;
#pragma unroll
            for (int i = 0; i < 12; i++) att += fA[i] * c[i];
            float ex = __expf(att);
            float sm_ = ex;
            sm_ += __shfl_xor_sync(mask, sm_, 1);
            sm_ += __shfl_xor_sync(mask, sm_, 2);
            sm_ += __shfl_xor_sync(mask, sm_, 4);
            float p = __fdividef(ex, sm_);
#pragma unroll
            for (int i = 0; i < 12; i++) acc[i] += p * fA[i];
        }
        // overflow edges streamed from L2, order-preserving
        for (int e2 = cached; e2 < deg; e2++) {
            const uint2* gz = (const uint2*)(zh_in + (size_t)g_colsrc[s + e2] * D + cap * FAC);
            uint2 A0 = gz[0], A1 = gz[1], A2 = gz[2];
            float fA[12];
            cvt12(A0, A1, A2, fA);
            float att = 0.f;
#pragma unroll
            for (int i = 0; i < 12; i++) att += fA[i] * c[i];
            float ex = __expf(att);
            float sm_ = ex;
            sm_ += __shfl_xor_sync(mask, sm_, 1);
            sm_ += __shfl_xor_sync(mask, sm_, 2);
            sm_ += __shfl_xor_sync(mask, sm_, 4);
            float p = __fdividef(ex, sm_);
#pragma unroll
            for (int i = 0; i < 12; i++) acc[i] += p * fA[i];
        }

        float v[12];
        float ss = 0.f;
#pragma unroll
        for (int i = 0; i < 12; i++) { v[i] = z[i] + acc[i]; ss += v[i] * v[i]; }
        float rn = rsqrtf(ss + 1e-12f);
#pragma unroll
        for (int i = 0; i < 12; i++) c[i] = v[i] * rn;
    }

    if (valid) {
#pragma unroll
        for (int i = 0; i < 12; i++) c[i] = fmaxf(c[i], 0.f);  // relu
        if (mode == 0) {
            // z_next = l2norm(relu(c)); write fp32 + fp16 buffers
            float ss = 0.f;
#pragma unroll
            for (int i = 0; i < 12; i++) ss += c[i] * c[i];
            float rn = rsqrtf(ss + 1e-12f);
#pragma unroll
            for (int i = 0; i < 12; i++) c[i] *= rn;
            float4* zp = (float4*)(z32_out + (size_t)node * D + cap * FAC);
            zp[0] = make_float4(c[0], c[1], c[2], c[3]);
            zp[1] = make_float4(c[4], c[5], c[6], c[7]);
            zp[2] = make_float4(c[8], c[9], c[10], c[11]);
            uint2* zh = (uint2*)(zh_out + (size_t)node * D + cap * FAC);
            __half2 h0 = __floats2half2_rn(c[0], c[1]);
            __half2 h1 = __floats2half2_rn(c[2], c[3]);
            __half2 h2 = __floats2half2_rn(c[4], c[5]);
            __half2 h3 = __floats2half2_rn(c[6], c[7]);
            __half2 h4 = __floats2half2_rn(c[8], c[9]);
            __half2 h5 = __floats2half2_rn(c[10], c[11]);
            zh[0] = make_uint2(*(unsigned*)&h0, *(unsigned*)&h1);
            zh[1] = make_uint2(*(unsigned*)&h2, *(unsigned*)&h3);
            zh[2] = make_uint2(*(unsigned*)&h4, *(unsigned*)&h5);
        } else {
            float4* fo = (float4*)(fout + (size_t)node * D + cap * FAC);
            fo[0] = make_float4(c[0], c[1], c[2], c[3]);
            fo[1] = make_float4(c[4], c[5], c[6], c[7]);
            fo[2] = make_float4(c[8], c[9], c[10], c[11]);
        }
    }
}

// ---------------------------------------------------------------------------
extern "C" void kernel_launch(void* const* d_in, const int* in_sizes, int n_in,
                              void* d_out, int out_size) {
    const float* X     = (const float*)d_in[0];
    const int*   edges = (const int*)d_in[1];
    const float* W     = (const float*)d_in[2];
    const float* b     = (const float*)d_in[3];
    int n = in_sizes[0] / 256;   // 50000
    int m = in_sizes[1] / 2;     // 800000

    cudaFuncSetAttribute(routing_layer,
                         cudaFuncAttributeMaxDynamicSharedMemorySize, ROUTE_SMEM);

    __half* zha; cudaGetSymbolAddress((void**)&zha, g_zh_a);
    __half* zhb; cudaGetSymbolAddress((void**)&zhb, g_zh_b);
    float* z32a; cudaGetSymbolAddress((void**)&z32a, g_z32_a);
    float* z32b; cudaGetSymbolAddress((void**)&z32b, g_z32_b);

    // zero + W transpose, then init layer
    zero_wt_kernel<<<(n + 255) / 256, 256>>>(W, n);
    init_gemm<<<(n + 31) / 32, 96>>>(X, b, n);

    // CSR by dst (deterministic: rows sorted by src)
    hist_kernel<<<(m + 255) / 256, 256>>>(edges, m);
    int sblocks = (n + 1023) / 1024;   // 49 <= 64
    scan1_kernel<<<sblocks, 1024>>>(n);
    scan2_kernel<<<1, 64>>>(sblocks, n);
    scan3_kernel<<<(n + 255) / 256, 256>>>(n);
    scatter_kernel<<<(m + 255) / 256, 256>>>(edges, m);
    sort_rows<<<(n + 255) / 256, 256>>>(n);

    // degree-balanced node permutation
    dhist_kernel<<<(n + 255) / 256, 256>>>(n);
    dscan_kernel<<<1, 32>>>();
    dscatter_kernel<<<(n + 255) / 256, 256>>>(n);

    // one-time prep, then 4 fused routing layers (z double-buffered)
    prep_kernel<<<(n * KCAP + 255) / 256, 256>>>(n);
    int blocks = (n + 15) / 16;
    routing_layer<<<blocks, 128, ROUTE_SMEM>>>(zha, z32a, zhb, z32b, nullptr, n, 0);
    routing_layer<<<blocks, 128, ROUTE_SMEM>>>(zhb, z32b, zha, z32a, nullptr, n, 0);
    routing_layer<<<blocks, 128, ROUTE_SMEM>>>(zha, z32a, zhb, z32b, nullptr, n, 0);
    routing_layer<<<blocks, 128, ROUTE_SMEM>>>(zhb, z32b, nullptr, nullptr, (float*)d_out, n, 1);
}

// round 7
// speedup vs baseline: 1.6307x; 1.0285x over previous
#include <cuda_runtime.h>
#include <cuda_fp16.h>

// Problem constants (fixed shapes)
#define N_MAX 50000
#define M_MAX 800000
#define D 96          // K*FAC
#define KCAP 8
#define FAC 12

#define CAP 18                        // cached neighbors per node in smem (fp16)
#define WSLAB (CAP * 768)             // per-warp slab: CAP entries x 768B
#define ROUTE_SMEM (4 * WSLAB)        // 55296 B per 128-thread block -> 4 blocks/SM

// Static scratch (no allocations allowed)
__device__ __half g_zh_a[N_MAX * D];   // fp16 z double-buffer A (gather source)
__device__ __half g_zh_b[N_MAX * D];   // fp16 z double-buffer B
__device__ float  g_z32_a[N_MAX * D];  // fp32 z double-buffer A (self-term)
__device__ float  g_z32_b[N_MAX * D];  // fp32 z double-buffer B
__device__ float  g_c[N_MAX * D];      // init-layer output (pre-norm)
__device__ float  g_wt[D * 256];       // W transposed to [out=96][in=256]
__device__ int    g_deg[N_MAX];
__device__ int    g_rowptr[N_MAX + 1];
__device__ int    g_cursor[N_MAX];
__device__ int    g_colsrc[M_MAX];
__device__ int    g_bsum[64];
__device__ int    g_boff[64];
__device__ int    g_dhist[64];
__device__ int    g_dcur[64];
__device__ int    g_perm[N_MAX];

// 8-lane group sum (3-shuffle butterfly; fp32 redux unsupported on sm_103)
__device__ __forceinline__ float gsum8(float v, unsigned mask) {
    v += __shfl_xor_sync(mask, v, 1);
    v += __shfl_xor_sync(mask, v, 2);
    v += __shfl_xor_sync(mask, v, 4);
    return v;
}

// ---------------------------------------------------------------------------
// zero + W transpose fused. W_init [K,256,FAC] -> g_wt [96][256]
__global__ void zero_wt_kernel(const float* __restrict__ W, int n) {
    int i = blockIdx.x * blockDim.x + threadIdx.x;
    if (i < n) g_deg[i] = 0;
    if (i < 64) g_dhist[i] = 0;
    if (i < D * 256) {
        int o = i >> 8, c = i & 255;
        int k = o / FAC, oo = o % FAC;
        g_wt[i] = W[k * (256 * FAC) + c * FAC + oo];
    }
}

// ---------------------------------------------------------------------------
// Init layer: g_c[n][o] = relu( X[n,:] . Wt[o,:] + b[o] )
__global__ void __launch_bounds__(96) init_gemm(const float* __restrict__ X,
                                                const float* __restrict__ bv, int n) {
    __shared__ float xs[32][256];
    int t = threadIdx.x;
    int nb = blockIdx.x * 32;
    for (int j = t; j < 32 * 256; j += 96) {
        int q = j >> 8;
        xs[q][j & 255] = (nb + q < n) ? X[nb * 256 + j] : 0.f;
    }
    __syncthreads();

    float acc[32];
#pragma unroll
    for (int q = 0; q < 32; q++) acc[q] = 0.f;

    const float4* wrow = (const float4*)(g_wt + t * 256);
#pragma unroll 2
    for (int i4 = 0; i4 < 64; i4++) {
        float4 w = wrow[i4];
#pragma unroll
        for (int q = 0; q < 32; q++) {
            float4 xv = *(const float4*)&xs[q][i4 * 4];
            acc[q] += w.x * xv.x + w.y * xv.y + w.z * xv.z + w.w * xv.w;
        }
    }
    float bb = bv[t];
    int cnt = min(32, n - nb);
    for (int q = 0; q < cnt; q++)
        g_c[(nb + q) * D + t] = fmaxf(acc[q] + bb, 0.f);
}

// ---------------------------------------------------------------------------
// CSR build: hist -> 3-phase hierarchical scan -> scatter -> per-row sort
__global__ void hist_kernel(const int* __restrict__ edges, int m) {
    int e = blockIdx.x * blockDim.x + threadIdx.x;
    if (e < m) atomicAdd(&g_deg[edges[m + e]], 1);
}

__global__ void scan1_kernel(int n) {
    __shared__ int wsum[32];
    int t = threadIdx.x, lane = t & 31, wid = t >> 5;
    int idx = blockIdx.x * 1024 + t;
    int v = (idx < n) ? g_deg[idx] : 0;
    int x = v;
#pragma unroll
    for (int off = 1; off < 32; off <<= 1) {
        int y = __shfl_up_sync(0xffffffffu, x, off);
        if (lane >= off) x += y;
    }
    if (lane == 31) wsum[wid] = x;
    __syncthreads();
    if (wid == 0) {
        int w = wsum[lane];
#pragma unroll
        for (int off = 1; off < 32; off <<= 1) {
            int y = __shfl_up_sync(0xffffffffu, w, off);
            if (lane >= off) w += y;
        }
        wsum[lane] = w;
    }
    __syncthreads();
    int pre = (wid > 0) ? wsum[wid - 1] : 0;
    if (idx < n) g_rowptr[idx] = pre + x - v;   // block-local exclusive
    if (t == 1023) g_bsum[blockIdx.x] = pre + x;
}

__global__ void scan2_kernel(int nblocks, int n) {
    int t = threadIdx.x;  // 64 threads
    int v = (t < nblocks) ? g_bsum[t] : 0;
    int x = v;
    int lane = t & 31, wid = t >> 5;
    __shared__ int ws[2];
#pragma unroll
    for (int off = 1; off < 32; off <<= 1) {
        int y = __shfl_up_sync(0xffffffffu, x, off);
        if (lane >= off) x += y;
    }
    if (lane == 31) ws[wid] = x;
    __syncthreads();
    int add = (wid == 1) ? ws[0] : 0;
    g_boff[t] = add + x - v;
    if (t == 63) g_rowptr[n] = add + x;
}

__global__ void scan3_kernel(int n) {
    int idx = blockIdx.x * blockDim.x + threadIdx.x;
    if (idx < n) {
        int r = g_rowptr[idx] + g_boff[idx >> 10];
        g_rowptr[idx] = r;
        g_cursor[idx] = r;
    }
}

__global__ void scatter_kernel(const int* __restrict__ edges, int m) {
    int e = blockIdx.x * blockDim.x + threadIdx.x;
    if (e < m) {
        int d = edges[m + e];
        int pos = atomicAdd(&g_cursor[d], 1);
        g_colsrc[pos] = edges[e];
    }
}

// Sort each row's src list: deterministic accumulation order.
__global__ void sort_rows(int n) {
    int node = blockIdx.x * blockDim.x + threadIdx.x;
    if (node >= n) return;
    int s = g_rowptr[node], e = g_rowptr[node + 1];
    for (int i = s + 1; i < e; i++) {
        int v = g_colsrc[i];
        int j = i - 1;
        while (j >= s && g_colsrc[j] > v) { g_colsrc[j + 1] = g_colsrc[j]; j--; }
        g_colsrc[j + 1] = v;
    }
}

// ---------------------------------------------------------------------------
// Degree-balanced permutation (bucket by clamped degree), smem-local hist.
__global__ void dhist_kernel(int n) {
    __shared__ int h[64];
    if (threadIdx.x < 64) h[threadIdx.x] = 0;
    __syncthreads();
    int i = blockIdx.x * blockDim.x + threadIdx.x;
    if (i < n) atomicAdd(&h[min(g_deg[i], 63)], 1);
    __syncthreads();
    if (threadIdx.x < 64 && h[threadIdx.x]) atomicAdd(&g_dhist[threadIdx.x], h[threadIdx.x]);
}

__global__ void dscan_kernel() {
    if (threadIdx.x == 0) {
        int run = 0;
        for (int i = 0; i < 64; i++) { g_dcur[i] = run; run += g_dhist[i]; }
    }
}

__global__ void dscatter_kernel(int n) {
    int i = blockIdx.x * blockDim.x + threadIdx.x;
    if (i < n) {
        int pos = atomicAdd(&g_dcur[min(g_deg[i], 63)], 1);
        g_perm[pos] = i;
    }
}

// ---------------------------------------------------------------------------
// One-time prep after init: z_a = l2norm(relu(g_c)) -> fp32 + fp16 buffers.
__global__ void prep_kernel(int n) {
    int idx = blockIdx.x * blockDim.x + threadIdx.x;
    if (idx >= n * KCAP) return;
    const float4* cp = (const float4*)(g_c + idx * FAC);
    float4 a0 = cp[0], a1 = cp[1], a2 = cp[2];
    float t[12] = {a0.x, a0.y, a0.z, a0.w, a1.x, a1.y, a1.z, a1.w,
                   a2.x, a2.y, a2.z, a2.w};
    float s = 0.f;
#pragma unroll
    for (int i = 0; i < 12; i++) { t[i] = fmaxf(t[i], 0.f); s += t[i] * t[i]; }
    float rn = rsqrtf(s + 1e-12f);
#pragma unroll
    for (int i = 0; i < 12; i++) t[i] *= rn;
    float4* zp = (float4*)(g_z32_a + idx * FAC);
    zp[0] = make_float4(t[0], t[1], t[2], t[3]);
    zp[1] = make_float4(t[4], t[5], t[6], t[7]);
    zp[2] = make_float4(t[8], t[9], t[10], t[11]);
    uint2* zh = (uint2*)(g_zh_a + idx * FAC);
    __half2 h0 = __floats2half2_rn(t[0], t[1]);
    __half2 h1 = __floats2half2_rn(t[2], t[3]);
    __half2 h2 = __floats2half2_rn(t[4], t[5]);
    __half2 h3 = __floats2half2_rn(t[6], t[7]);
    __half2 h4 = __floats2half2_rn(t[8], t[9]);
    __half2 h5 = __floats2half2_rn(t[10], t[11]);
    zh[0] = make_uint2(*(unsigned*)&h0, *(unsigned*)&h1);
    zh[1] = make_uint2(*(unsigned*)&h2, *(unsigned*)&h3);
    zh[2] = make_uint2(*(unsigned*)&h4, *(unsigned*)&h5);
}

// ---------------------------------------------------------------------------
__device__ __forceinline__ void cvt12(uint2 a0, uint2 a1, uint2 a2, float* f) {
    float2 t;
    t = __half22float2(*(__half2*)&a0.x); f[0] = t.x;  f[1] = t.y;
    t = __half22float2(*(__half2*)&a0.y); f[2] = t.x;  f[3] = t.y;
    t = __half22float2(*(__half2*)&a1.x); f[4] = t.x;  f[5] = t.y;
    t = __half22float2(*(__half2*)&a1.y); f[6] = t.x;  f[7] = t.y;
    t = __half22float2(*(__half2*)&a2.x); f[8] = t.x;  f[9] = t.y;
    t = __half22float2(*(__half2*)&a2.y); f[10] = t.x; f[11] = t.y;
}

// Fused routing layer with conflict-free warp-interleaved smem layout:
// entry e of a warp's slab = [j in 0..2][lane][8B]  (768 B per entry).
// Each lane reads back exactly the bytes it wrote (no cross-lane smem dep).
// 8 lanes per node (lane = capsule), 4 nodes/warp, 16 nodes/block, 4 blocks/SM.
// mode 0: write z_next = l2norm(relu(c)) to zh_out (fp16) + z32_out (fp32).
// mode 1: write relu(c) to fout (final output).
__global__ void __launch_bounds__(128, 4)
routing_layer(const __half* __restrict__ zh_in, const float* __restrict__ z32_in,
              __half* __restrict__ zh_out, float* __restrict__ z32_out,
              float* __restrict__ fout, int n, int mode) {
    extern __shared__ char sm[];
    int lane = threadIdx.x & 31;
    int warp = threadIdx.x >> 5;
    int group = lane >> 3;
    int cap = lane & 7;
    unsigned mask = 0xFFu << (group << 3);
    int local = warp * 4 + group;
    int slot = blockIdx.x * 16 + local;
    bool valid = slot < n;
    int node = valid ? g_perm[slot] : 0;

    int s = 0, deg = 0;
    if (valid) { s = g_rowptr[node]; deg = g_rowptr[node + 1] - s; }
    int cached = min(deg, CAP);

    char* wslab = sm + warp * WSLAB;

    // ---- fill: gather cached neighbor z rows into interleaved layout ----
    for (int e = 0; e < cached; e++) {
        int src = g_colsrc[s + e];
        const uint2* gz = (const uint2*)(zh_in + (size_t)src * D) + cap * 3;
        uint2 d0 = gz[0], d1 = gz[1], d2 = gz[2];
        char* base = wslab + e * 768 + lane * 8;
        *(uint2*)(base)       = d0;
        *(uint2*)(base + 256) = d1;
        *(uint2*)(base + 512) = d2;
    }

    // ---- z_self (fp32); c init = z ----
    float z[12], c[12];
    if (valid) {
        const float4* zb = (const float4*)(z32_in + (size_t)node * D + cap * FAC);
        float4 a0 = zb[0], a1 = zb[1], a2 = zb[2];
        z[0] = a0.x; z[1] = a0.y; z[2]  = a0.z; z[3]  = a0.w;
        z[4] = a1.x; z[5] = a1.y; z[6]  = a1.z; z[7]  = a1.w;
        z[8] = a2.x; z[9] = a2.y; z[10] = a2.z; z[11] = a2.w;
#pragma unroll
        for (int i = 0; i < 12; i++) c[i] = z[i];
    }
    __syncwarp();

    // ---- 6 routing iterations from smem / registers ----
    for (int it = 0; it < 6; it++) {
        float acc[12];
#pragma unroll
        for (int i = 0; i < 12; i++) acc[i] = 0.f;

        int e = 0;
        // 2-edge unrolled: two independent chains in flight
        for (; e + 1 < cached; e += 2) {
            const char* pA = wslab + e * 768 + lane * 8;
            const char* pB = pA + 768;
            uint2 A0 = *(const uint2*)pA;
            uint2 A1 = *(const uint2*)(pA + 256);
            uint2 A2 = *(const uint2*)(pA + 512);
            uint2 B0 = *(const uint2*)pB;
            uint2 B1 = *(const uint2*)(pB + 256);
            uint2 B2 = *(const uint2*)(pB + 512);
            float fA[12], fB[12];
            cvt12(A0, A1, A2, fA);
            cvt12(B0, B1, B2, fB);
            // dot as partial trees
            float aA0 = fA[0]*c[0] + fA[1]*c[1] + fA[2]*c[2] + fA[3]*c[3];
            float aA1 = fA[4]*c[4] + fA[5]*c[5] + fA[6]*c[6] + fA[7]*c[7];
            float aA2 = fA[8]*c[8] + fA[9]*c[9] + fA[10]*c[10] + fA[11]*c[11];
            float aB0 = fB[0]*c[0] + fB[1]*c[1] + fB[2]*c[2] + fB[3]*c[3];
            float aB1 = fB[4]*c[4] + fB[5]*c[5] + fB[6]*c[6] + fB[7]*c[7];
            float aB2 = fB[8]*c[8] + fB[9]*c[9] + fB[10]*c[10] + fB[11]*c[11];
            // z,c unit vectors -> att in [-1,1]: exp safe without max-sub
            float exA = __expf(aA0 + aA1 + aA2);
            float exB = __expf(aB0 + aB1 + aB2);
            float sA = gsum8(exA, mask);
            float sB = gsum8(exB, mask);
            float pAp = __fdividef(exA, sA);
            float pBp = __fdividef(exB, sB);
#pragma unroll
            for (int i = 0; i < 12; i++) acc[i] += pAp * fA[i];
#pragma unroll
            for (int i = 0; i < 12; i++) acc[i] += pBp * fB[i];
        }
        if (e < cached) {
            const char* pA = wslab + e * 768 + lane * 8;
            uint2 A0 = *(const uint2*)pA;
            uint2 A1 = *(const uint2*)(pA + 256);
            uint2 A2 = *(const uint2*)(pA + 512);
            float fA[12];
            cvt12(A0, A1, A2, fA);
            float a0 = fA[0]*c[0] + fA[1]*c[1] + fA[2]*c[2] + fA[3]*c[3];
            float a1 = fA[4]*c[4] + fA[5]*c[5] + fA[6]*c[6] + fA[7]*c[7];
            float a2 = fA[8]*c[8] + fA[9]*c[9] + fA[10]*c[10] + fA[11]*c[11];
            float ex = __expf(a0 + a1 + a2);
            float sm_ = gsum8(ex, mask);
            float p = __fdividef(ex, sm_);
#pragma unroll
            for (int i = 0; i < 12; i++) acc[i] += p * fA[i];
        }
        // overflow edges streamed from L2, order-preserving
        for (int e2 = cached; e2 < deg; e2++) {
            const uint2* gz = (const uint2*)(zh_in + (size_t)g_colsrc[s + e2] * D + cap * FAC);
            uint2 A0 = gz[0], A1 = gz[1], A2 = gz[2];
            float fA[12];
            cvt12(A0, A1, A2, fA);
            float a0 = fA[0]*c[0] + fA[1]*c[1] + fA[2]*c[2] + fA[3]*c[3];
            float a1 = fA[4]*c[4] + fA[5]*c[5] + fA[6]*c[6] + fA[7]*c[7];
            float a2 = fA[8]*c[8] + fA[9]*c[9] + fA[10]*c[10] + fA[11]*c[11];
            float ex = __expf(a0 + a1 + a2);
            float sm_ = gsum8(ex, mask);
            float p = __fdividef(ex, sm_);
#pragma unroll
            for (int i = 0; i < 12; i++) acc[i] += p * fA[i];
        }

        float v[12];
        float ss = 0.f;
#pragma unroll
        for (int i = 0; i < 12; i++) { v[i] = z[i] + acc[i]; ss += v[i] * v[i]; }
        float rn = rsqrtf(ss + 1e-12f);
#pragma unroll
        for (int i = 0; i < 12; i++) c[i] = v[i] * rn;
    }

    if (valid) {
#pragma unroll
        for (int i = 0; i < 12; i++) c[i] = fmaxf(c[i], 0.f);  // relu
        if (mode == 0) {
            float ss = 0.f;
#pragma unroll
            for (int i = 0; i < 12; i++) ss += c[i] * c[i];
            float rn = rsqrtf(ss + 1e-12f);
#pragma unroll
            for (int i = 0; i < 12; i++) c[i] *= rn;
            float4* zp = (float4*)(z32_out + (size_t)node * D + cap * FAC);
            zp[0] = make_float4(c[0], c[1], c[2], c[3]);
            zp[1] = make_float4(c[4], c[5], c[6], c[7]);
            zp[2] = make_float4(c[8], c[9], c[10], c[11]);
            uint2* zh = (uint2*)(zh_out + (size_t)node * D + cap * FAC);
            __half2 h0 = __floats2half2_rn(c[0], c[1]);
            __half2 h1 = __floats2half2_rn(c[2], c[3]);
            __half2 h2 = __floats2half2_rn(c[4], c[5]);
            __half2 h3 = __floats2half2_rn(c[6], c[7]);
            __half2 h4 = __floats2half2_rn(c[8], c[9]);
            __half2 h5 = __floats2half2_rn(c[10], c[11]);
            zh[0] = make_uint2(*(unsigned*)&h0, *(unsigned*)&h1);
            zh[1] = make_uint2(*(unsigned*)&h2, *(unsigned*)&h3);
            zh[2] = make_uint2(*(unsigned*)&h4, *(unsigned*)&h5);
        } else {
            float4* fo = (float4*)(fout + (size_t)node * D + cap * FAC);
            fo[0] = make_float4(c[0], c[1], c[2], c[3]);
            fo[1] = make_float4(c[4], c[5], c[6], c[7]);
            fo[2] = make_float4(c[8], c[9], c[10], c[11]);
        }
    }
}

// ---------------------------------------------------------------------------
extern "C" void kernel_launch(void* const* d_in, const int* in_sizes, int n_in,
                              void* d_out, int out_size) {
    const float* X     = (const float*)d_in[0];
    const int*   edges = (const int*)d_in[1];
    const float* W     = (const float*)d_in[2];
    const float* b     = (const float*)d_in[3];
    int n = in_sizes[0] / 256;   // 50000
    int m = in_sizes[1] / 2;     // 800000

    cudaFuncSetAttribute(routing_layer,
                         cudaFuncAttributeMaxDynamicSharedMemorySize, ROUTE_SMEM);

    __half* zha; cudaGetSymbolAddress((void**)&zha, g_zh_a);
    __half* zhb; cudaGetSymbolAddress((void**)&zhb, g_zh_b);
    float* z32a; cudaGetSymbolAddress((void**)&z32a, g_z32_a);
    float* z32b; cudaGetSymbolAddress((void**)&z32b, g_z32_b);

    // zero + W transpose, then init layer
    zero_wt_kernel<<<(n + 255) / 256, 256>>>(W, n);
    init_gemm<<<(n + 31) / 32, 96>>>(X, b, n);

    // CSR by dst (deterministic: rows sorted by src)
    hist_kernel<<<(m + 255) / 256, 256>>>(edges, m);
    int sblocks = (n + 1023) / 1024;   // 49 <= 64
    scan1_kernel<<<sblocks, 1024>>>(n);
    scan2_kernel<<<1, 64>>>(sblocks, n);
    scan3_kernel<<<(n + 255) / 256, 256>>>(n);
    scatter_kernel<<<(m + 255) / 256, 256>>>(edges, m);
    sort_rows<<<(n + 255) / 256, 256>>>(n);

    // degree-balanced node permutation
    dhist_kernel<<<(n + 255) / 256, 256>>>(n);
    dscan_kernel<<<1, 32>>>();
    dscatter_kernel<<<(n + 255) / 256, 256>>>(n);

    // one-time prep, then 4 fused routing layers (z double-buffered)
    prep_kernel<<<(n * KCAP + 255) / 256, 256>>>(n);
    int blocks = (n + 15) / 16;
    routing_layer<<<blocks, 128, ROUTE_SMEM>>>(zha, z32a, zhb, z32b, nullptr, n, 0);
    routing_layer<<<blocks, 128, ROUTE_SMEM>>>(zhb, z32b, zha, z32a, nullptr, n, 0);
    routing_layer<<<blocks, 128, ROUTE_SMEM>>>(zha, z32a, zhb, z32b, nullptr, n, 0);
    routing_layer<<<blocks, 128, ROUTE_SMEM>>>(zhb, z32b, nullptr, nullptr, (float*)d_out, n, 1);
}

// round 8
// speedup vs baseline: 1.8793x; 1.1524x over previous
#include <cuda_runtime.h>
#include <cuda_fp16.h>

// Problem constants (fixed shapes)
#define N_MAX 50000
#define M_MAX 800000
#define D 96          // K*FAC
#define KCAP 8
#define FAC 12

#define CAP 18                        // cached neighbors per node in smem (fp16)
#define WSLAB (CAP * 768)             // per-warp slab: CAP entries x 768B
#define ROUTE_SMEM (4 * WSLAB)        // 55296 B per 128-thread block -> 4 blocks/SM

// Static scratch (no allocations allowed)
__device__ __half g_zh_a[N_MAX * D];   // fp16 z double-buffer A (gather source)
__device__ __half g_zh_b[N_MAX * D];   // fp16 z double-buffer B
__device__ float  g_z32_a[N_MAX * D];  // fp32 z double-buffer A (self-term)
__device__ float  g_z32_b[N_MAX * D];  // fp32 z double-buffer B
__device__ float  g_c[N_MAX * D];      // init-layer output (pre-norm)
__device__ float  g_wt[D * 256];       // W transposed to [out=96][in=256]
__device__ int    g_deg[N_MAX];
__device__ int    g_rowptr[N_MAX + 1];
__device__ int    g_cursor[N_MAX];
__device__ int    g_colsrc[M_MAX];
__device__ int    g_bsum[64];
__device__ int    g_boff[64];
__device__ int    g_dhist[64];
__device__ int    g_dcur[64];
__device__ int    g_perm[N_MAX];

// 8-lane group sum (3-shuffle butterfly; fp32 redux unsupported on sm_103)
__device__ __forceinline__ float gsum8(float v, unsigned mask) {
    v += __shfl_xor_sync(mask, v, 1);
    v += __shfl_xor_sync(mask, v, 2);
    v += __shfl_xor_sync(mask, v, 4);
    return v;
}

// ---------------------------------------------------------------------------
// zero + W transpose fused. W_init [K,256,FAC] -> g_wt [96][256]
__global__ void zero_wt_kernel(const float* __restrict__ W, int n) {
    int i = blockIdx.x * blockDim.x + threadIdx.x;
    if (i < n) g_deg[i] = 0;
    if (i < 64) g_dhist[i] = 0;
    if (i < D * 256) {
        int o = i >> 8, c = i & 255;
        int k = o / FAC, oo = o % FAC;
        g_wt[i] = W[k * (256 * FAC) + c * FAC + oo];
    }
}

// ---------------------------------------------------------------------------
// Init layer: g_c[n][o] = relu( X[n,:] . Wt[o,:] + b[o] )
__global__ void __launch_bounds__(96) init_gemm(const float* __restrict__ X,
                                                const float* __restrict__ bv, int n) {
    __shared__ float xs[32][256];
    int t = threadIdx.x;
    int nb = blockIdx.x * 32;
    for (int j = t; j < 32 * 256; j += 96) {
        int q = j >> 8;
        xs[q][j & 255] = (nb + q < n) ? X[nb * 256 + j] : 0.f;
    }
    __syncthreads();

    float acc[32];
#pragma unroll
    for (int q = 0; q < 32; q++) acc[q] = 0.f;

    const float4* wrow = (const float4*)(g_wt + t * 256);
#pragma unroll 2
    for (int i4 = 0; i4 < 64; i4++) {
        float4 w = wrow[i4];
#pragma unroll
        for (int q = 0; q < 32; q++) {
            float4 xv = *(const float4*)&xs[q][i4 * 4];
            acc[q] += w.x * xv.x + w.y * xv.y + w.z * xv.z + w.w * xv.w;
        }
    }
    float bb = bv[t];
    int cnt = min(32, n - nb);
    for (int q = 0; q < cnt; q++)
        g_c[(nb + q) * D + t] = fmaxf(acc[q] + bb, 0.f);
}

// ---------------------------------------------------------------------------
// CSR build: hist -> 3-phase hierarchical scan -> scatter -> per-row sort
__global__ void hist_kernel(const int* __restrict__ edges, int m) {
    int e = blockIdx.x * blockDim.x + threadIdx.x;
    if (e < m) atomicAdd(&g_deg[edges[m + e]], 1);
}

__global__ void scan1_kernel(int n) {
    __shared__ int wsum[32];
    int t = threadIdx.x, lane = t & 31, wid = t >> 5;
    int idx = blockIdx.x * 1024 + t;
    int v = (idx < n) ? g_deg[idx] : 0;
    int x = v;
#pragma unroll
    for (int off = 1; off < 32; off <<= 1) {
        int y = __shfl_up_sync(0xffffffffu, x, off);
        if (lane >= off) x += y;
    }
    if (lane == 31) wsum[wid] = x;
    __syncthreads();
    if (wid == 0) {
        int w = wsum[lane];
#pragma unroll
        for (int off = 1; off < 32; off <<= 1) {
            int y = __shfl_up_sync(0xffffffffu, w, off);
            if (lane >= off) w += y;
        }
        wsum[lane] = w;
    }
    __syncthreads();
    int pre = (wid > 0) ? wsum[wid - 1] : 0;
    if (idx < n) g_rowptr[idx] = pre + x - v;   // block-local exclusive
    if (t == 1023) g_bsum[blockIdx.x] = pre + x;
}

__global__ void scan2_kernel(int nblocks, int n) {
    int t = threadIdx.x;  // 64 threads
    int v = (t < nblocks) ? g_bsum[t] : 0;
    int x = v;
    int lane = t & 31, wid = t >> 5;
    __shared__ int ws[2];
#pragma unroll
    for (int off = 1; off < 32; off <<= 1) {
        int y = __shfl_up_sync(0xffffffffu, x, off);
        if (lane >= off) x += y;
    }
    if (lane == 31) ws[wid] = x;
    __syncthreads();
    int add = (wid == 1) ? ws[0] : 0;
    g_boff[t] = add + x - v;
    if (t == 63) g_rowptr[n] = add + x;
}

__global__ void scan3_kernel(int n) {
    int idx = blockIdx.x * blockDim.x + threadIdx.x;
    if (idx < n) {
        int r = g_rowptr[idx] + g_boff[idx >> 10];
        g_rowptr[idx] = r;
        g_cursor[idx] = r;
    }
}

__global__ void scatter_kernel(const int* __restrict__ edges, int m) {
    int e = blockIdx.x * blockDim.x + threadIdx.x;
    if (e < m) {
        int d = edges[m + e];
        int pos = atomicAdd(&g_cursor[d], 1);
        g_colsrc[pos] = edges[e];
    }
}

// Sort each row's src list: deterministic accumulation order.
__global__ void sort_rows(int n) {
    int node = blockIdx.x * blockDim.x + threadIdx.x;
    if (node >= n) return;
    int s = g_rowptr[node], e = g_rowptr[node + 1];
    for (int i = s + 1; i < e; i++) {
        int v = g_colsrc[i];
        int j = i - 1;
        while (j >= s && g_colsrc[j] > v) { g_colsrc[j + 1] = g_colsrc[j]; j--; }
        g_colsrc[j + 1] = v;
    }
}

// ---------------------------------------------------------------------------
// Degree-balanced permutation (bucket by clamped degree), smem-local hist.
__global__ void dhist_kernel(int n) {
    __shared__ int h[64];
    if (threadIdx.x < 64) h[threadIdx.x] = 0;
    __syncthreads();
    int i = blockIdx.x * blockDim.x + threadIdx.x;
    if (i < n) atomicAdd(&h[min(g_deg[i], 63)], 1);
    __syncthreads();
    if (threadIdx.x < 64 && h[threadIdx.x]) atomicAdd(&g_dhist[threadIdx.x], h[threadIdx.x]);
}

__global__ void dscan_kernel() {
    if (threadIdx.x == 0) {
        int run = 0;
        for (int i = 0; i < 64; i++) { g_dcur[i] = run; run += g_dhist[i]; }
    }
}

__global__ void dscatter_kernel(int n) {
    int i = blockIdx.x * blockDim.x + threadIdx.x;
    if (i < n) {
        int pos = atomicAdd(&g_dcur[min(g_deg[i], 63)], 1);
        g_perm[pos] = i;
    }
}

// ---------------------------------------------------------------------------
// One-time prep after init: z_a = l2norm(relu(g_c)) -> fp32 + fp16 buffers.
__global__ void prep_kernel(int n) {
    int idx = blockIdx.x * blockDim.x + threadIdx.x;
    if (idx >= n * KCAP) return;
    const float4* cp = (const float4*)(g_c + idx * FAC);
    float4 a0 = cp[0], a1 = cp[1], a2 = cp[2];
    float t[12] = {a0.x, a0.y, a0.z, a0.w, a1.x, a1.y, a1.z, a1.w,
                   a2.x, a2.y, a2.z, a2.w};
    float s = 0.f;
#pragma unroll
    for (int i = 0; i < 12; i++) { t[i] = fmaxf(t[i], 0.f); s += t[i] * t[i]; }
    float rn = rsqrtf(s + 1e-12f);
#pragma unroll
    for (int i = 0; i < 12; i++) t[i] *= rn;
    float4* zp = (float4*)(g_z32_a + idx * FAC);
    zp[0] = make_float4(t[0], t[1], t[2], t[3]);
    zp[1] = make_float4(t[4], t[5], t[6], t[7]);
    zp[2] = make_float4(t[8], t[9], t[10], t[11]);
    uint2* zh = (uint2*)(g_zh_a + idx * FAC);
    __half2 h0 = __floats2half2_rn(t[0], t[1]);
    __half2 h1 = __floats2half2_rn(t[2], t[3]);
    __half2 h2 = __floats2half2_rn(t[4], t[5]);
    __half2 h3 = __floats2half2_rn(t[6], t[7]);
    __half2 h4 = __floats2half2_rn(t[8], t[9]);
    __half2 h5 = __floats2half2_rn(t[10], t[11]);
    zh[0] = make_uint2(*(unsigned*)&h0, *(unsigned*)&h1);
    zh[1] = make_uint2(*(unsigned*)&h2, *(unsigned*)&h3);
    zh[2] = make_uint2(*(unsigned*)&h4, *(unsigned*)&h5);
}

// ---------------------------------------------------------------------------
__device__ __forceinline__ void cvt12(uint2 a0, uint2 a1, uint2 a2, float* f) {
    float2 t;
    t = __half22float2(*(__half2*)&a0.x); f[0] = t.x;  f[1] = t.y;
    t = __half22float2(*(__half2*)&a0.y); f[2] = t.x;  f[3] = t.y;
    t = __half22float2(*(__half2*)&a1.x); f[4] = t.x;  f[5] = t.y;
    t = __half22float2(*(__half2*)&a1.y); f[6] = t.x;  f[7] = t.y;
    t = __half22float2(*(__half2*)&a2.x); f[8] = t.x;  f[9] = t.y;
    t = __half22float2(*(__half2*)&a2.y); f[10] = t.x; f[11] = t.y;
}

// Fused routing layer, conflict-free warp-interleaved smem layout.
// Descending-degree schedule (high-degree nodes launch in wave 0) and
// software-pipelined overflow loop (LDG latency off the serial chain).
// 8 lanes per node (lane = capsule), 4 nodes/warp, 16 nodes/block, 4 blocks/SM.
// mode 0: write z_next = l2norm(relu(c)) to zh_out (fp16) + z32_out (fp32).
// mode 1: write relu(c) to fout (final output).
__global__ void __launch_bounds__(128, 4)
routing_layer(const __half* __restrict__ zh_in, const float* __restrict__ z32_in,
              __half* __restrict__ zh_out, float* __restrict__ z32_out,
              float* __restrict__ fout, int n, int mode) {
    extern __shared__ char sm[];
    int lane = threadIdx.x & 31;
    int warp = threadIdx.x >> 5;
    int group = lane >> 3;
    int cap = lane & 7;
    unsigned mask = 0xFFu << (group << 3);
    int local = warp * 4 + group;
    int slot = blockIdx.x * 16 + local;
    bool valid = slot < n;
    int node = valid ? g_perm[(n - 1) - slot] : 0;   // descending degree

    int s = 0, deg = 0;
    if (valid) { s = g_rowptr[node]; deg = g_rowptr[node + 1] - s; }
    int cached = min(deg, CAP);

    char* wslab = sm + warp * WSLAB;

    // ---- fill: gather cached neighbor z rows into interleaved layout ----
    for (int e = 0; e < cached; e++) {
        int src = g_colsrc[s + e];
        const uint2* gz = (const uint2*)(zh_in + (size_t)src * D) + cap * 3;
        uint2 d0 = gz[0], d1 = gz[1], d2 = gz[2];
        char* base = wslab + e * 768 + lane * 8;
        *(uint2*)(base)       = d0;
        *(uint2*)(base + 256) = d1;
        *(uint2*)(base + 512) = d2;
    }

    // ---- z_self (fp32); c init = z ----
    float z[12], c[12];
    if (valid) {
        const float4* zb = (const float4*)(z32_in + (size_t)node * D + cap * FAC);
        float4 a0 = zb[0], a1 = zb[1], a2 = zb[2];
        z[0] = a0.x; z[1] = a0.y; z[2]  = a0.z; z[3]  = a0.w;
        z[4] = a1.x; z[5] = a1.y; z[6]  = a1.z; z[7]  = a1.w;
        z[8] = a2.x; z[9] = a2.y; z[10] = a2.z; z[11] = a2.w;
#pragma unroll
        for (int i = 0; i < 12; i++) c[i] = z[i];
    }
    __syncwarp();

    // ---- 6 routing iterations from smem / registers ----
    for (int it = 0; it < 6; it++) {
        float acc[12];
#pragma unroll
        for (int i = 0; i < 12; i++) acc[i] = 0.f;

        int e = 0;
        // 2-edge unrolled: two independent chains in flight
        for (; e + 1 < cached; e += 2) {
            const char* pA = wslab + e * 768 + lane * 8;
            const char* pB = pA + 768;
            uint2 A0 = *(const uint2*)pA;
            uint2 A1 = *(const uint2*)(pA + 256);
            uint2 A2 = *(const uint2*)(pA + 512);
            uint2 B0 = *(const uint2*)pB;
            uint2 B1 = *(const uint2*)(pB + 256);
            uint2 B2 = *(const uint2*)(pB + 512);
            float fA[12], fB[12];
            cvt12(A0, A1, A2, fA);
            cvt12(B0, B1, B2, fB);
            float aA0 = fA[0]*c[0] + fA[1]*c[1] + fA[2]*c[2] + fA[3]*c[3];
            float aA1 = fA[4]*c[4] + fA[5]*c[5] + fA[6]*c[6] + fA[7]*c[7];
            float aA2 = fA[8]*c[8] + fA[9]*c[9] + fA[10]*c[10] + fA[11]*c[11];
            float aB0 = fB[0]*c[0] + fB[1]*c[1] + fB[2]*c[2] + fB[3]*c[3];
            float aB1 = fB[4]*c[4] + fB[5]*c[5] + fB[6]*c[6] + fB[7]*c[7];
            float aB2 = fB[8]*c[8] + fB[9]*c[9] + fB[10]*c[10] + fB[11]*c[11];
            // z,c unit vectors -> att in [-1,1]: exp safe without max-sub
            float exA = __expf(aA0 + aA1 + aA2);
            float exB = __expf(aB0 + aB1 + aB2);
            float sA = gsum8(exA, mask);
            float sB = gsum8(exB, mask);
            float pAp = __fdividef(exA, sA);
            float pBp = __fdividef(exB, sB);
#pragma unroll
            for (int i = 0; i < 12; i++) acc[i] += pAp * fA[i];
#pragma unroll
            for (int i = 0; i < 12; i++) acc[i] += pBp * fB[i];
        }
        if (e < cached) {
            const char* pA = wslab + e * 768 + lane * 8;
            uint2 A0 = *(const uint2*)pA;
            uint2 A1 = *(const uint2*)(pA + 256);
            uint2 A2 = *(const uint2*)(pA + 512);
            float fA[12];
            cvt12(A0, A1, A2, fA);
            float a0 = fA[0]*c[0] + fA[1]*c[1] + fA[2]*c[2] + fA[3]*c[3];
            float a1 = fA[4]*c[4] + fA[5]*c[5] + fA[6]*c[6] + fA[7]*c[7];
            float a2 = fA[8]*c[8] + fA[9]*c[9] + fA[10]*c[10] + fA[11]*c[11];
            float ex = __expf(a0 + a1 + a2);
            float sm_ = gsum8(ex, mask);
            float p = __fdividef(ex, sm_);
#pragma unroll
            for (int i = 0; i < 12; i++) acc[i] += p * fA[i];
        }
        // overflow edges streamed from L2, software-pipelined (prefetch depth 1)
        {
            int e2 = cached;
            uint2 P0, P1, P2;
            if (e2 < deg) {
                const uint2* gz = (const uint2*)(zh_in + (size_t)g_colsrc[s + e2] * D + cap * FAC);
                P0 = gz[0]; P1 = gz[1]; P2 = gz[2];
            }
            for (; e2 < deg; e2++) {
                uint2 A0 = P0, A1 = P1, A2 = P2;
                if (e2 + 1 < deg) {
                    const uint2* gz = (const uint2*)(zh_in + (size_t)g_colsrc[s + e2 + 1] * D + cap * FAC);
                    P0 = gz[0]; P1 = gz[1]; P2 = gz[2];
                }
                float fA[12];
                cvt12(A0, A1, A2, fA);
                float a0 = fA[0]*c[0] + fA[1]*c[1] + fA[2]*c[2] + fA[3]*c[3];
                float a1 = fA[4]*c[4] + fA[5]*c[5] + fA[6]*c[6] + fA[7]*c[7];
                float a2 = fA[8]*c[8] + fA[9]*c[9] + fA[10]*c[10] + fA[11]*c[11];
                float ex = __expf(a0 + a1 + a2);
                float sm_ = gsum8(ex, mask);
                float p = __fdividef(ex, sm_);
#pragma unroll
                for (int i = 0; i < 12; i++) acc[i] += p * fA[i];
            }
        }

        float v[12];
        float ss = 0.f;
#pragma unroll
        for (int i = 0; i < 12; i++) { v[i] = z[i] + acc[i]; ss += v[i] * v[i]; }
        float rn = rsqrtf(ss + 1e-12f);
#pragma unroll
        for (int i = 0; i < 12; i++) c[i] = v[i] * rn;
    }

    if (valid) {
#pragma unroll
        for (int i = 0; i < 12; i++) c[i] = fmaxf(c[i], 0.f);  // relu
        if (mode == 0) {
            float ss = 0.f;
#pragma unroll
            for (int i = 0; i < 12; i++) ss += c[i] * c[i];
            float rn = rsqrtf(ss + 1e-12f);
#pragma unroll
            for (int i = 0; i < 12; i++) c[i] *= rn;
            float4* zp = (float4*)(z32_out + (size_t)node * D + cap * FAC);
            zp[0] = make_float4(c[0], c[1], c[2], c[3]);
            zp[1] = make_float4(c[4], c[5], c[6], c[7]);
            zp[2] = make_float4(c[8], c[9], c[10], c[11]);
            uint2* zh = (uint2*)(zh_out + (size_t)node * D + cap * FAC);
            __half2 h0 = __floats2half2_rn(c[0], c[1]);
            __half2 h1 = __floats2half2_rn(c[2], c[3]);
            __half2 h2 = __floats2half2_rn(c[4], c[5]);
            __half2 h3 = __floats2half2_rn(c[6], c[7]);
            __half2 h4 = __floats2half2_rn(c[8], c[9]);
            __half2 h5 = __floats2half2_rn(c[10], c[11]);
            zh[0] = make_uint2(*(unsigned*)&h0, *(unsigned*)&h1);
            zh[1] = make_uint2(*(unsigned*)&h2, *(unsigned*)&h3);
            zh[2] = make_uint2(*(unsigned*)&h4, *(unsigned*)&h5);
        } else {
            float4* fo = (float4*)(fout + (size_t)node * D + cap * FAC);
            fo[0] = make_float4(c[0], c[1], c[2], c[3]);
            fo[1] = make_float4(c[4], c[5], c[6], c[7]);
            fo[2] = make_float4(c[8], c[9], c[10], c[11]);
        }
    }
}

// ---------------------------------------------------------------------------
extern "C" void kernel_launch(void* const* d_in, const int* in_sizes, int n_in,
                              void* d_out, int out_size) {
    const float* X     = (const float*)d_in[0];
    const int*   edges = (const int*)d_in[1];
    const float* W     = (const float*)d_in[2];
    const float* b     = (const float*)d_in[3];
    int n = in_sizes[0] / 256;   // 50000
    int m = in_sizes[1] / 2;     // 800000

    cudaFuncSetAttribute(routing_layer,
                         cudaFuncAttributeMaxDynamicSharedMemorySize, ROUTE_SMEM);

    __half* zha; cudaGetSymbolAddress((void**)&zha, g_zh_a);
    __half* zhb; cudaGetSymbolAddress((void**)&zhb, g_zh_b);
    float* z32a; cudaGetSymbolAddress((void**)&z32a, g_z32_a);
    float* z32b; cudaGetSymbolAddress((void**)&z32b, g_z32_b);

    // zero + W transpose, then init layer
    zero_wt_kernel<<<(n + 255) / 256, 256>>>(W, n);
    init_gemm<<<(n + 31) / 32, 96>>>(X, b, n);

    // CSR by dst (deterministic: rows sorted by src)
    hist_kernel<<<(m + 255) / 256, 256>>>(edges, m);
    int sblocks = (n + 1023) / 1024;   // 49 <= 64
    scan1_kernel<<<sblocks, 1024>>>(n);
    scan2_kernel<<<1, 64>>>(sblocks, n);
    scan3_kernel<<<(n + 255) / 256, 256>>>(n);
    scatter_kernel<<<(m + 255) / 256, 256>>>(edges, m);
    sort_rows<<<(n + 255) / 256, 256>>>(n);

    // degree-balanced node permutation
    dhist_kernel<<<(n + 255) / 256, 256>>>(n);
    dscan_kernel<<<1, 32>>>();
    dscatter_kernel<<<(n + 255) / 256, 256>>>(n);

    // one-time prep, then 4 fused routing layers (z double-buffered)
    prep_kernel<<<(n * KCAP + 255) / 256, 256>>>(n);
    int blocks = (n + 15) / 16;
    routing_layer<<<blocks, 128, ROUTE_SMEM>>>(zha, z32a, zhb, z32b, nullptr, n, 0);
    routing_layer<<<blocks, 128, ROUTE_SMEM>>>(zhb, z32b, zha, z32a, nullptr, n, 0);
    routing_layer<<<blocks, 128, ROUTE_SMEM>>>(zha, z32a, zhb, z32b, nullptr, n, 0);
    routing_layer<<<blocks, 128, ROUTE_SMEM>>>(zhb, z32b, nullptr, nullptr, (float*)d_out, n, 1);
}

// round 9
// speedup vs baseline: 1.9153x; 1.0192x over previous
#include <cuda_runtime.h>
#include <cuda_fp16.h>

// Problem constants (fixed shapes)
#define N_MAX 50000
#define M_MAX 800000
#define D 96          // K*FAC
#define KCAP 8
#define FAC 12

#define CAP 18                        // cached neighbors per node in smem (fp16)
#define WSLAB (CAP * 768)             // per-warp slab: CAP entries x 768B
#define ROUTE_SMEM (4 * WSLAB)        // 55296 B per 128-thread block -> 4 blocks/SM

// Static scratch (no allocations allowed)
__device__ __half g_zh_a[N_MAX * D];   // fp16 z double-buffer A (gather source)
__device__ __half g_zh_b[N_MAX * D];   // fp16 z double-buffer B
__device__ float  g_z32_a[N_MAX * D];  // fp32 z double-buffer A (self-term)
__device__ float  g_z32_b[N_MAX * D];  // fp32 z double-buffer B
__device__ float  g_c[N_MAX * D];      // init-layer output (pre-norm)
__device__ float  g_wt[D * 256];       // W transposed to [out=96][in=256]
__device__ int    g_deg[N_MAX];
__device__ int    g_rowptr[N_MAX + 1];
__device__ int    g_cursor[N_MAX];
__device__ int    g_colsrc[M_MAX];
__device__ int    g_bsum[64];
__device__ int    g_boff[64];
__device__ int    g_dhist[64];
__device__ int    g_dcur[64];
__device__ int    g_perm[N_MAX];

// 8-lane group sum (3-shuffle butterfly; fp32 redux unsupported on sm_103)
__device__ __forceinline__ float gsum8(float v, unsigned mask) {
    v += __shfl_xor_sync(mask, v, 1);
    v += __shfl_xor_sync(mask, v, 2);
    v += __shfl_xor_sync(mask, v, 4);
    return v;
}

// ---------------------------------------------------------------------------
// zero + W transpose fused. W_init [K,256,FAC] -> g_wt [96][256]
__global__ void zero_wt_kernel(const float* __restrict__ W, int n) {
    int i = blockIdx.x * blockDim.x + threadIdx.x;
    if (i < n) g_deg[i] = 0;
    if (i < 64) g_dhist[i] = 0;
    if (i < D * 256) {
        int o = i >> 8, c = i & 255;
        int k = o / FAC, oo = o % FAC;
        g_wt[i] = W[k * (256 * FAC) + c * FAC + oo];
    }
}

// ---------------------------------------------------------------------------
// Init layer: g_c[n][o] = relu( X[n,:] . Wt[o,:] + b[o] )
__global__ void __launch_bounds__(96) init_gemm(const float* __restrict__ X,
                                                const float* __restrict__ bv, int n) {
    __shared__ float xs[32][256];
    int t = threadIdx.x;
    int nb = blockIdx.x * 32;
    for (int j = t; j < 32 * 256; j += 96) {
        int q = j >> 8;
        xs[q][j & 255] = (nb + q < n) ? X[nb * 256 + j] : 0.f;
    }
    __syncthreads();

    float acc[32];
#pragma unroll
    for (int q = 0; q < 32; q++) acc[q] = 0.f;

    const float4* wrow = (const float4*)(g_wt + t * 256);
#pragma unroll 2
    for (int i4 = 0; i4 < 64; i4++) {
        float4 w = wrow[i4];
#pragma unroll
        for (int q = 0; q < 32; q++) {
            float4 xv = *(const float4*)&xs[q][i4 * 4];
            acc[q] += w.x * xv.x + w.y * xv.y + w.z * xv.z + w.w * xv.w;
        }
    }
    float bb = bv[t];
    int cnt = min(32, n - nb);
    for (int q = 0; q < cnt; q++)
        g_c[(nb + q) * D + t] = fmaxf(acc[q] + bb, 0.f);
}

// ---------------------------------------------------------------------------
// CSR build: hist -> 3-phase hierarchical scan -> scatter -> per-row sort
__global__ void hist_kernel(const int* __restrict__ edges, int m) {
    int e = blockIdx.x * blockDim.x + threadIdx.x;
    if (e < m) atomicAdd(&g_deg[edges[m + e]], 1);
}

__global__ void scan1_kernel(int n) {
    __shared__ int wsum[32];
    int t = threadIdx.x, lane = t & 31, wid = t >> 5;
    int idx = blockIdx.x * 1024 + t;
    int v = (idx < n) ? g_deg[idx] : 0;
    int x = v;
#pragma unroll
    for (int off = 1; off < 32; off <<= 1) {
        int y = __shfl_up_sync(0xffffffffu, x, off);
        if (lane >= off) x += y;
    }
    if (lane == 31) wsum[wid] = x;
    __syncthreads();
    if (wid == 0) {
        int w = wsum[lane];
#pragma unroll
        for (int off = 1; off < 32; off <<= 1) {
            int y = __shfl_up_sync(0xffffffffu, w, off);
            if (lane >= off) w += y;
        }
        wsum[lane] = w;
    }
    __syncthreads();
    int pre = (wid > 0) ? wsum[wid - 1] : 0;
    if (idx < n) g_rowptr[idx] = pre + x - v;   // block-local exclusive
    if (t == 1023) g_bsum[blockIdx.x] = pre + x;
}

__global__ void scan2_kernel(int nblocks, int n) {
    int t = threadIdx.x;  // 64 threads
    int v = (t < nblocks) ? g_bsum[t] : 0;
    int x = v;
    int lane = t & 31, wid = t >> 5;
    __shared__ int ws[2];
#pragma unroll
    for (int off = 1; off < 32; off <<= 1) {
        int y = __shfl_up_sync(0xffffffffu, x, off);
        if (lane >= off) x += y;
    }
    if (lane == 31) ws[wid] = x;
    __syncthreads();
    int add = (wid == 1) ? ws[0] : 0;
    g_boff[t] = add + x - v;
    if (t == 63) g_rowptr[n] = add + x;
}

__global__ void scan3_kernel(int n) {
    int idx = blockIdx.x * blockDim.x + threadIdx.x;
    if (idx < n) {
        int r = g_rowptr[idx] + g_boff[idx >> 10];
        g_rowptr[idx] = r;
        g_cursor[idx] = r;
    }
}

__global__ void scatter_kernel(const int* __restrict__ edges, int m) {
    int e = blockIdx.x * blockDim.x + threadIdx.x;
    if (e < m) {
        int d = edges[m + e];
        int pos = atomicAdd(&g_cursor[d], 1);
        g_colsrc[pos] = edges[e];
    }
}

// Sort each row's src list: deterministic accumulation order.
__global__ void sort_rows(int n) {
    int node = blockIdx.x * blockDim.x + threadIdx.x;
    if (node >= n) return;
    int s = g_rowptr[node], e = g_rowptr[node + 1];
    for (int i = s + 1; i < e; i++) {
        int v = g_colsrc[i];
        int j = i - 1;
        while (j >= s && g_colsrc[j] > v) { g_colsrc[j + 1] = g_colsrc[j]; j--; }
        g_colsrc[j + 1] = v;
    }
}

// ---------------------------------------------------------------------------
// Degree-balanced permutation (bucket by clamped degree), smem-local hist.
__global__ void dhist_kernel(int n) {
    __shared__ int h[64];
    if (threadIdx.x < 64) h[threadIdx.x] = 0;
    __syncthreads();
    int i = blockIdx.x * blockDim.x + threadIdx.x;
    if (i < n) atomicAdd(&h[min(g_deg[i], 63)], 1);
    __syncthreads();
    if (threadIdx.x < 64 && h[threadIdx.x]) atomicAdd(&g_dhist[threadIdx.x], h[threadIdx.x]);
}

__global__ void dscan_kernel() {
    if (threadIdx.x == 0) {
        int run = 0;
        for (int i = 0; i < 64; i++) { g_dcur[i] = run; run += g_dhist[i]; }
    }
}

__global__ void dscatter_kernel(int n) {
    int i = blockIdx.x * blockDim.x + threadIdx.x;
    if (i < n) {
        int pos = atomicAdd(&g_dcur[min(g_deg[i], 63)], 1);
        g_perm[pos] = i;
    }
}

// ---------------------------------------------------------------------------
// One-time prep after init: z_a = l2norm(relu(g_c)) -> fp32 + fp16 buffers.
__global__ void prep_kernel(int n) {
    int idx = blockIdx.x * blockDim.x + threadIdx.x;
    if (idx >= n * KCAP) return;
    const float4* cp = (const float4*)(g_c + idx * FAC);
    float4 a0 = cp[0], a1 = cp[1], a2 = cp[2];
    float t[12] = {a0.x, a0.y, a0.z, a0.w, a1.x, a1.y, a1.z, a1.w,
                   a2.x, a2.y, a2.z, a2.w};
    float s = 0.f;
#pragma unroll
    for (int i = 0; i < 12; i++) { t[i] = fmaxf(t[i], 0.f); s += t[i] * t[i]; }
    float rn = rsqrtf(s + 1e-12f);
#pragma unroll
    for (int i = 0; i < 12; i++) t[i] *= rn;
    float4* zp = (float4*)(g_z32_a + idx * FAC);
    zp[0] = make_float4(t[0], t[1], t[2], t[3]);
    zp[1] = make_float4(t[4], t[5], t[6], t[7]);
    zp[2] = make_float4(t[8], t[9], t[10], t[11]);
    uint2* zh = (uint2*)(g_zh_a + idx * FAC);
    __half2 h0 = __floats2half2_rn(t[0], t[1]);
    __half2 h1 = __floats2half2_rn(t[2], t[3]);
    __half2 h2 = __floats2half2_rn(t[4], t[5]);
    __half2 h3 = __floats2half2_rn(t[6], t[7]);
    __half2 h4 = __floats2half2_rn(t[8], t[9]);
    __half2 h5 = __floats2half2_rn(t[10], t[11]);
    zh[0] = make_uint2(*(unsigned*)&h0, *(unsigned*)&h1);
    zh[1] = make_uint2(*(unsigned*)&h2, *(unsigned*)&h3);
    zh[2] = make_uint2(*(unsigned*)&h4, *(unsigned*)&h5);
}

// ---------------------------------------------------------------------------
__device__ __forceinline__ void cvt12(uint2 a0, uint2 a1, uint2 a2, float* f) {
    float2 t;
    t = __half22float2(*(__half2*)&a0.x); f[0] = t.x;  f[1] = t.y;
    t = __half22float2(*(__half2*)&a0.y); f[2] = t.x;  f[3] = t.y;
    t = __half22float2(*(__half2*)&a1.x); f[4] = t.x;  f[5] = t.y;
    t = __half22float2(*(__half2*)&a1.y); f[6] = t.x;  f[7] = t.y;
    t = __half22float2(*(__half2*)&a2.x); f[8] = t.x;  f[9] = t.y;
    t = __half22float2(*(__half2*)&a2.y); f[10] = t.x; f[11] = t.y;
}

// load one interleaved smem entry (3x uint2) and convert to 12 floats
__device__ __forceinline__ void ld_entry(const char* p, float* f) {
    uint2 a0 = *(const uint2*)p;
    uint2 a1 = *(const uint2*)(p + 256);
    uint2 a2 = *(const uint2*)(p + 512);
    cvt12(a0, a1, a2, f);
}

__device__ __forceinline__ float dot12(const float* f, const float* c) {
    float a0 = f[0]*c[0] + f[1]*c[1] + f[2]*c[2] + f[3]*c[3];
    float a1 = f[4]*c[4] + f[5]*c[5] + f[6]*c[6] + f[7]*c[7];
    float a2 = f[8]*c[8] + f[9]*c[9] + f[10]*c[10] + f[11]*c[11];
    return a0 + a1 + a2;
}

// Fused routing layer, conflict-free warp-interleaved smem layout,
// descending-degree schedule, 4-edge unrolled inner loop (16 concurrent
// chains per SMSP for latency hiding), software-pipelined overflow.
// 8 lanes per node (lane = capsule), 4 nodes/warp, 16 nodes/block, 4 blocks/SM.
// mode 0: write z_next = l2norm(relu(c)) to zh_out (fp16) + z32_out (fp32).
// mode 1: write relu(c) to fout (final output).
__global__ void __launch_bounds__(128, 4)
routing_layer(const __half* __restrict__ zh_in, const float* __restrict__ z32_in,
              __half* __restrict__ zh_out, float* __restrict__ z32_out,
              float* __restrict__ fout, int n, int mode) {
    extern __shared__ char sm[];
    int lane = threadIdx.x & 31;
    int warp = threadIdx.x >> 5;
    int group = lane >> 3;
    int cap = lane & 7;
    unsigned mask = 0xFFu << (group << 3);
    int local = warp * 4 + group;
    int slot = blockIdx.x * 16 + local;
    bool valid = slot < n;
    int node = valid ? g_perm[(n - 1) - slot] : 0;   // descending degree

    int s = 0, deg = 0;
    if (valid) { s = g_rowptr[node]; deg = g_rowptr[node + 1] - s; }
    int cached = min(deg, CAP);

    char* wslab = sm + warp * WSLAB;

    // ---- fill: gather cached neighbor z rows, src index prefetched ----
    {
        int e = 0;
        int src = (e < cached) ? g_colsrc[s + e] : 0;
        for (; e < cached; e++) {
            int nsrc = (e + 1 < cached) ? g_colsrc[s + e + 1] : 0;
            const uint2* gz = (const uint2*)(zh_in + (size_t)src * D) + cap * 3;
            uint2 d0 = gz[0], d1 = gz[1], d2 = gz[2];
            char* base = wslab + e * 768 + lane * 8;
            *(uint2*)(base)       = d0;
            *(uint2*)(base + 256) = d1;
            *(uint2*)(base + 512) = d2;
            src = nsrc;
        }
    }

    // ---- z_self (fp32); c init = z ----
    float z[12], c[12];
    if (valid) {
        const float4* zb = (const float4*)(z32_in + (size_t)node * D + cap * FAC);
        float4 a0 = zb[0], a1 = zb[1], a2 = zb[2];
        z[0] = a0.x; z[1] = a0.y; z[2]  = a0.z; z[3]  = a0.w;
        z[4] = a1.x; z[5] = a1.y; z[6]  = a1.z; z[7]  = a1.w;
        z[8] = a2.x; z[9] = a2.y; z[10] = a2.z; z[11] = a2.w;
#pragma unroll
        for (int i = 0; i < 12; i++) c[i] = z[i];
    }
    __syncwarp();

    // ---- 6 routing iterations from smem / registers ----
    for (int it = 0; it < 6; it++) {
        float acc[12];
#pragma unroll
        for (int i = 0; i < 12; i++) acc[i] = 0.f;

        int e = 0;
        // 4-edge unrolled: four independent chains in flight
        for (; e + 3 < cached; e += 4) {
            const char* p0 = wslab + e * 768 + lane * 8;
            float f0[12], f1[12], f2[12], f3[12];
            ld_entry(p0,        f0);
            ld_entry(p0 + 768,  f1);
            ld_entry(p0 + 1536, f2);
            ld_entry(p0 + 2304, f3);
            float ex0 = __expf(dot12(f0, c));
            float ex1 = __expf(dot12(f1, c));
            float ex2 = __expf(dot12(f2, c));
            float ex3 = __expf(dot12(f3, c));
            float s0 = gsum8(ex0, mask);
            float s1 = gsum8(ex1, mask);
            float s2 = gsum8(ex2, mask);
            float s3 = gsum8(ex3, mask);
            float p0_ = __fdividef(ex0, s0);
            float p1_ = __fdividef(ex1, s1);
            float p2_ = __fdividef(ex2, s2);
            float p3_ = __fdividef(ex3, s3);
#pragma unroll
            for (int i = 0; i < 12; i++)
                acc[i] += p0_ * f0[i] + p1_ * f1[i] + p2_ * f2[i] + p3_ * f3[i];
        }
        // 2-edge remainder
        for (; e + 1 < cached; e += 2) {
            const char* p0 = wslab + e * 768 + lane * 8;
            float f0[12], f1[12];
            ld_entry(p0,       f0);
            ld_entry(p0 + 768, f1);
            float ex0 = __expf(dot12(f0, c));
            float ex1 = __expf(dot12(f1, c));
            float s0 = gsum8(ex0, mask);
            float s1 = gsum8(ex1, mask);
            float p0_ = __fdividef(ex0, s0);
            float p1_ = __fdividef(ex1, s1);
#pragma unroll
            for (int i = 0; i < 12; i++) acc[i] += p0_ * f0[i] + p1_ * f1[i];
        }
        if (e < cached) {
            const char* p0 = wslab + e * 768 + lane * 8;
            float f0[12];
            ld_entry(p0, f0);
            float ex = __expf(dot12(f0, c));
            float sm_ = gsum8(ex, mask);
            float p = __fdividef(ex, sm_);
#pragma unroll
            for (int i = 0; i < 12; i++) acc[i] += p * f0[i];
        }
        // overflow edges streamed from L2, software-pipelined (prefetch depth 1)
        {
            int e2 = cached;
            uint2 P0, P1, P2;
            if (e2 < deg) {
                const uint2* gz = (const uint2*)(zh_in + (size_t)g_colsrc[s + e2] * D + cap * FAC);
                P0 = gz[0]; P1 = gz[1]; P2 = gz[2];
            }
            for (; e2 < deg; e2++) {
                uint2 A0 = P0, A1 = P1, A2 = P2;
                if (e2 + 1 < deg) {
                    const uint2* gz = (const uint2*)(zh_in + (size_t)g_colsrc[s + e2 + 1] * D + cap * FAC);
                    P0 = gz[0]; P1 = gz[1]; P2 = gz[2];
                }
                float fA[12];
                cvt12(A0, A1, A2, fA);
                float ex = __expf(dot12(fA, c));
                float sm_ = gsum8(ex, mask);
                float p = __fdividef(ex, sm_);
#pragma unroll
                for (int i = 0; i < 12; i++) acc[i] += p * fA[i];
            }
        }

        float v[12];
        float ss = 0.f;
#pragma unroll
        for (int i = 0; i < 12; i++) { v[i] = z[i] + acc[i]; ss += v[i] * v[i]; }
        float rn = rsqrtf(ss + 1e-12f);
#pragma unroll
        for (int i = 0; i < 12; i++) c[i] = v[i] * rn;
    }

    if (valid) {
#pragma unroll
        for (int i = 0; i < 12; i++) c[i] = fmaxf(c[i], 0.f);  // relu
        if (mode == 0) {
            float ss = 0.f;
#pragma unroll
            for (int i = 0; i < 12; i++) ss += c[i] * c[i];
            float rn = rsqrtf(ss + 1e-12f);
#pragma unroll
            for (int i = 0; i < 12; i++) c[i] *= rn;
            float4* zp = (float4*)(z32_out + (size_t)node * D + cap * FAC);
            zp[0] = make_float4(c[0], c[1], c[2], c[3]);
            zp[1] = make_float4(c[4], c[5], c[6], c[7]);
            zp[2] = make_float4(c[8], c[9], c[10], c[11]);
            uint2* zh = (uint2*)(zh_out + (size_t)node * D + cap * FAC);
            __half2 h0 = __floats2half2_rn(c[0], c[1]);
            __half2 h1 = __floats2half2_rn(c[2], c[3]);
            __half2 h2 = __floats2half2_rn(c[4], c[5]);
            __half2 h3 = __floats2half2_rn(c[6], c[7]);
            __half2 h4 = __floats2half2_rn(c[8], c[9]);
            __half2 h5 = __floats2half2_rn(c[10], c[11]);
            zh[0] = make_uint2(*(unsigned*)&h0, *(unsigned*)&h1);
            zh[1] = make_uint2(*(unsigned*)&h2, *(unsigned*)&h3);
            zh[2] = make_uint2(*(unsigned*)&h4, *(unsigned*)&h5);
        } else {
            float4* fo = (float4*)(fout + (size_t)node * D + cap * FAC);
            fo[0] = make_float4(c[0], c[1], c[2], c[3]);
            fo[1] = make_float4(c[4], c[5], c[6], c[7]);
            fo[2] = make_float4(c[8], c[9], c[10], c[11]);
        }
    }
}

// ---------------------------------------------------------------------------
extern "C" void kernel_launch(void* const* d_in, const int* in_sizes, int n_in,
                              void* d_out, int out_size) {
    const float* X     = (const float*)d_in[0];
    const int*   edges = (const int*)d_in[1];
    const float* W     = (const float*)d_in[2];
    const float* b     = (const float*)d_in[3];
    int n = in_sizes[0] / 256;   // 50000
    int m = in_sizes[1] / 2;     // 800000

    cudaFuncSetAttribute(routing_layer,
                         cudaFuncAttributeMaxDynamicSharedMemorySize, ROUTE_SMEM);

    __half* zha; cudaGetSymbolAddress((void**)&zha, g_zh_a);
    __half* zhb; cudaGetSymbolAddress((void**)&zhb, g_zh_b);
    float* z32a; cudaGetSymbolAddress((void**)&z32a, g_z32_a);
    float* z32b; cudaGetSymbolAddress((void**)&z32b, g_z32_b);

    // zero + W transpose, then init layer
    zero_wt_kernel<<<(n + 255) / 256, 256>>>(W, n);
    init_gemm<<<(n + 31) / 32, 96>>>(X, b, n);

    // CSR by dst (deterministic: rows sorted by src)
    hist_kernel<<<(m + 255) / 256, 256>>>(edges, m);
    int sblocks = (n + 1023) / 1024;   // 49 <= 64
    scan1_kernel<<<sblocks, 1024>>>(n);
    scan2_kernel<<<1, 64>>>(sblocks, n);
    scan3_kernel<<<(n + 255) / 256, 256>>>(n);
    scatter_kernel<<<(m + 255) / 256, 256>>>(edges, m);
    sort_rows<<<(n + 255) / 256, 256>>>(n);

    // degree-balanced node permutation
    dhist_kernel<<<(n + 255) / 256, 256>>>(n);
    dscan_kernel<<<1, 32>>>();
    dscatter_kernel<<<(n + 255) / 256, 256>>>(n);

    // one-time prep, then 4 fused routing layers (z double-buffered)
    prep_kernel<<<(n * KCAP + 255) / 256, 256>>>(n);
    int blocks = (n + 15) / 16;
    routing_layer<<<blocks, 128, ROUTE_SMEM>>>(zha, z32a, zhb, z32b, nullptr, n, 0);
    routing_layer<<<blocks, 128, ROUTE_SMEM>>>(zhb, z32b, zha, z32a, nullptr, n, 0);
    routing_layer<<<blocks, 128, ROUTE_SMEM>>>(zha, z32a, zhb, z32b, nullptr, n, 0);
    routing_layer<<<blocks, 128, ROUTE_SMEM>>>(zhb, z32b, nullptr, nullptr, (float*)d_out, n, 1);
}

// round 10
// speedup vs baseline: 1.9467x; 1.0164x over previous
#include <cuda_runtime.h>
#include <cuda_fp16.h>

// Problem constants (fixed shapes)
#define N_MAX 50000
#define M_MAX 800000
#define D 96          // K*FAC
#define KCAP 8
#define FAC 12

#define CAP 18                        // cached neighbors per node in smem (fp16)
#define WSLAB (CAP * 768)             // per-warp slab: CAP entries x 768B
#define ROUTE_SMEM (4 * WSLAB)        // 55296 B per 128-thread block -> 4 blocks/SM
#define ROUTE_GRID 592                // 148 SMs x 4 resident blocks: one wave

// Static scratch (no allocations allowed)
__device__ __half g_zh_a[N_MAX * D];   // fp16 z double-buffer A (gather source)
__device__ __half g_zh_b[N_MAX * D];   // fp16 z double-buffer B
__device__ float  g_z32_a[N_MAX * D];  // fp32 z double-buffer A (self-term)
__device__ float  g_z32_b[N_MAX * D];  // fp32 z double-buffer B
__device__ float  g_c[N_MAX * D];      // init-layer output (pre-norm)
__device__ float  g_wt[D * 256];       // W transposed to [out=96][in=256]
__device__ int    g_deg[N_MAX];
__device__ int    g_rowptr[N_MAX + 1];
__device__ int    g_cursor[N_MAX];
__device__ int    g_colsrc[M_MAX];
__device__ int    g_bsum[64];
__device__ int    g_boff[64];
__device__ int    g_dhist[64];
__device__ int    g_dcur[64];
__device__ int    g_perm[N_MAX];
__device__ int    g_work[4];           // per-layer work-stealing counters

// 8-lane group sum (3-shuffle butterfly; fp32 redux unsupported on sm_103)
__device__ __forceinline__ float gsum8(float v, unsigned mask) {
    v += __shfl_xor_sync(mask, v, 1);
    v += __shfl_xor_sync(mask, v, 2);
    v += __shfl_xor_sync(mask, v, 4);
    return v;
}

// ---------------------------------------------------------------------------
// zero + W transpose fused; also resets work-stealing counters each replay.
__global__ void zero_wt_kernel(const float* __restrict__ W, int n) {
    int i = blockIdx.x * blockDim.x + threadIdx.x;
    if (i < n) g_deg[i] = 0;
    if (i < 64) g_dhist[i] = 0;
    if (i < 4) g_work[i] = 0;
    if (i < D * 256) {
        int o = i >> 8, c = i & 255;
        int k = o / FAC, oo = o % FAC;
        g_wt[i] = W[k * (256 * FAC) + c * FAC + oo];
    }
}

// ---------------------------------------------------------------------------
// Init layer: g_c[n][o] = relu( X[n,:] . Wt[o,:] + b[o] )
__global__ void __launch_bounds__(96) init_gemm(const float* __restrict__ X,
                                                const float* __restrict__ bv, int n) {
    __shared__ float xs[32][256];
    int t = threadIdx.x;
    int nb = blockIdx.x * 32;
    for (int j = t; j < 32 * 256; j += 96) {
        int q = j >> 8;
        xs[q][j & 255] = (nb + q < n) ? X[nb * 256 + j] : 0.f;
    }
    __syncthreads();

    float acc[32];
#pragma unroll
    for (int q = 0; q < 32; q++) acc[q] = 0.f;

    const float4* wrow = (const float4*)(g_wt + t * 256);
#pragma unroll 2
    for (int i4 = 0; i4 < 64; i4++) {
        float4 w = wrow[i4];
#pragma unroll
        for (int q = 0; q < 32; q++) {
            float4 xv = *(const float4*)&xs[q][i4 * 4];
            acc[q] += w.x * xv.x + w.y * xv.y + w.z * xv.z + w.w * xv.w;
        }
    }
    float bb = bv[t];
    int cnt = min(32, n - nb);
    for (int q = 0; q < cnt; q++)
        g_c[(nb + q) * D + t] = fmaxf(acc[q] + bb, 0.f);
}

// ---------------------------------------------------------------------------
// CSR build: hist -> 3-phase hierarchical scan -> scatter -> per-row sort
__global__ void hist_kernel(const int* __restrict__ edges, int m) {
    int e = blockIdx.x * blockDim.x + threadIdx.x;
    if (e < m) atomicAdd(&g_deg[edges[m + e]], 1);
}

__global__ void scan1_kernel(int n) {
    __shared__ int wsum[32];
    int t = threadIdx.x, lane = t & 31, wid = t >> 5;
    int idx = blockIdx.x * 1024 + t;
    int v = (idx < n) ? g_deg[idx] : 0;
    int x = v;
#pragma unroll
    for (int off = 1; off < 32; off <<= 1) {
        int y = __shfl_up_sync(0xffffffffu, x, off);
        if (lane >= off) x += y;
    }
    if (lane == 31) wsum[wid] = x;
    __syncthreads();
    if (wid == 0) {
        int w = wsum[lane];
#pragma unroll
        for (int off = 1; off < 32; off <<= 1) {
            int y = __shfl_up_sync(0xffffffffu, w, off);
            if (lane >= off) w += y;
        }
        wsum[lane] = w;
    }
    __syncthreads();
    int pre = (wid > 0) ? wsum[wid - 1] : 0;
    if (idx < n) g_rowptr[idx] = pre + x - v;   // block-local exclusive
    if (t == 1023) g_bsum[blockIdx.x] = pre + x;
}

__global__ void scan2_kernel(int nblocks, int n) {
    int t = threadIdx.x;  // 64 threads
    int v = (t < nblocks) ? g_bsum[t] : 0;
    int x = v;
    int lane = t & 31, wid = t >> 5;
    __shared__ int ws[2];
#pragma unroll
    for (int off = 1; off < 32; off <<= 1) {
        int y = __shfl_up_sync(0xffffffffu, x, off);
        if (lane >= off) x += y;
    }
    if (lane == 31) ws[wid] = x;
    __syncthreads();
    int add = (wid == 1) ? ws[0] : 0;
    g_boff[t] = add + x - v;
    if (t == 63) g_rowptr[n] = add + x;
}

__global__ void scan3_kernel(int n) {
    int idx = blockIdx.x * blockDim.x + threadIdx.x;
    if (idx < n) {
        int r = g_rowptr[idx] + g_boff[idx >> 10];
        g_rowptr[idx] = r;
        g_cursor[idx] = r;
    }
}

__global__ void scatter_kernel(const int* __restrict__ edges, int m) {
    int e = blockIdx.x * blockDim.x + threadIdx.x;
    if (e < m) {
        int d = edges[m + e];
        int pos = atomicAdd(&g_cursor[d], 1);
        g_colsrc[pos] = edges[e];
    }
}

// Sort each row's src list: deterministic accumulation order.
__global__ void sort_rows(int n) {
    int node = blockIdx.x * blockDim.x + threadIdx.x;
    if (node >= n) return;
    int s = g_rowptr[node], e = g_rowptr[node + 1];
    for (int i = s + 1; i < e; i++) {
        int v = g_colsrc[i];
        int j = i - 1;
        while (j >= s && g_colsrc[j] > v) { g_colsrc[j + 1] = g_colsrc[j]; j--; }
        g_colsrc[j + 1] = v;
    }
}

// ---------------------------------------------------------------------------
// Degree-balanced permutation (bucket by clamped degree), smem-local hist.
__global__ void dhist_kernel(int n) {
    __shared__ int h[64];
    if (threadIdx.x < 64) h[threadIdx.x] = 0;
    __syncthreads();
    int i = blockIdx.x * blockDim.x + threadIdx.x;
    if (i < n) atomicAdd(&h[min(g_deg[i], 63)], 1);
    __syncthreads();
    if (threadIdx.x < 64 && h[threadIdx.x]) atomicAdd(&g_dhist[threadIdx.x], h[threadIdx.x]);
}

__global__ void dscan_kernel() {
    if (threadIdx.x == 0) {
        int run = 0;
        for (int i = 0; i < 64; i++) { g_dcur[i] = run; run += g_dhist[i]; }
    }
}

__global__ void dscatter_kernel(int n) {
    int i = blockIdx.x * blockDim.x + threadIdx.x;
    if (i < n) {
        int pos = atomicAdd(&g_dcur[min(g_deg[i], 63)], 1);
        g_perm[pos] = i;
    }
}

// ---------------------------------------------------------------------------
// One-time prep after init: z_a = l2norm(relu(g_c)) -> fp32 + fp16 buffers.
__global__ void prep_kernel(int n) {
    int idx = blockIdx.x * blockDim.x + threadIdx.x;
    if (idx >= n * KCAP) return;
    const float4* cp = (const float4*)(g_c + idx * FAC);
    float4 a0 = cp[0], a1 = cp[1], a2 = cp[2];
    float t[12] = {a0.x, a0.y, a0.z, a0.w, a1.x, a1.y, a1.z, a1.w,
                   a2.x, a2.y, a2.z, a2.w};
    float s = 0.f;
#pragma unroll
    for (int i = 0; i < 12; i++) { t[i] = fmaxf(t[i], 0.f); s += t[i] * t[i]; }
    float rn = rsqrtf(s + 1e-12f);
#pragma unroll
    for (int i = 0; i < 12; i++) t[i] *= rn;
    float4* zp = (float4*)(g_z32_a + idx * FAC);
    zp[0] = make_float4(t[0], t[1], t[2], t[3]);
    zp[1] = make_float4(t[4], t[5], t[6], t[7]);
    zp[2] = make_float4(t[8], t[9], t[10], t[11]);
    uint2* zh = (uint2*)(g_zh_a + idx * FAC);
    __half2 h0 = __floats2half2_rn(t[0], t[1]);
    __half2 h1 = __floats2half2_rn(t[2], t[3]);
    __half2 h2 = __floats2half2_rn(t[4], t[5]);
    __half2 h3 = __floats2half2_rn(t[6], t[7]);
    __half2 h4 = __floats2half2_rn(t[8], t[9]);
    __half2 h5 = __floats2half2_rn(t[10], t[11]);
    zh[0] = make_uint2(*(unsigned*)&h0, *(unsigned*)&h1);
    zh[1] = make_uint2(*(unsigned*)&h2, *(unsigned*)&h3);
    zh[2] = make_uint2(*(unsigned*)&h4, *(unsigned*)&h5);
}

// ---------------------------------------------------------------------------
__device__ __forceinline__ void cvt12(uint2 a0, uint2 a1, uint2 a2, float* f) {
    float2 t;
    t = __half22float2(*(__half2*)&a0.x); f[0] = t.x;  f[1] = t.y;
    t = __half22float2(*(__half2*)&a0.y); f[2] = t.x;  f[3] = t.y;
    t = __half22float2(*(__half2*)&a1.x); f[4] = t.x;  f[5] = t.y;
    t = __half22float2(*(__half2*)&a1.y); f[6] = t.x;  f[7] = t.y;
    t = __half22float2(*(__half2*)&a2.x); f[8] = t.x;  f[9] = t.y;
    t = __half22float2(*(__half2*)&a2.y); f[10] = t.x; f[11] = t.y;
}

// load one interleaved smem entry (3x uint2) and convert to 12 floats
__device__ __forceinline__ void ld_entry(const char* p, float* f) {
    uint2 a0 = *(const uint2*)p;
    uint2 a1 = *(const uint2*)(p + 256);
    uint2 a2 = *(const uint2*)(p + 512);
    cvt12(a0, a1, a2, f);
}

__device__ __forceinline__ float dot12(const float* f, const float* c) {
    float a0 = f[0]*c[0] + f[1]*c[1] + f[2]*c[2] + f[3]*c[3];
    float a1 = f[4]*c[4] + f[5]*c[5] + f[6]*c[6] + f[7]*c[7];
    float a2 = f[8]*c[8] + f[9]*c[9] + f[10]*c[10] + f[11]*c[11];
    return a0 + a1 + a2;
}

// Persistent work-stealing routing layer (single wave of 592 blocks; each
// block pulls 16-node chunks from a per-layer counter — descending-degree
// chunk order so the steal-tail is the cheapest work). Conflict-free
// warp-interleaved smem layout; 4-edge unrolled inner loop; pipelined
// overflow. Output mapping is chunk->nodes, so results are deterministic.
// mode 0: write z_next = l2norm(relu(c)); mode 1: write relu(c) to fout.
__global__ void __launch_bounds__(128, 4)
routing_layer(const __half* __restrict__ zh_in, const float* __restrict__ z32_in,
              __half* __restrict__ zh_out, float* __restrict__ z32_out,
              float* __restrict__ fout, int n, int mode, int widx) {
    extern __shared__ char sm[];
    __shared__ int chunk_s;
    int lane = threadIdx.x & 31;
    int warp = threadIdx.x >> 5;
    int group = lane >> 3;
    int cap = lane & 7;
    unsigned mask = 0xFFu << (group << 3);
    int local = warp * 4 + group;
    int nchunks = (n + 15) / 16;

    char* wslab = sm + warp * WSLAB;

    while (true) {
        if (threadIdx.x == 0) chunk_s = atomicAdd(&g_work[widx], 1);
        __syncthreads();
        int chunk = chunk_s;
        __syncthreads();   // chunk_s safe to overwrite next round
        if (chunk >= nchunks) break;

        int slot = chunk * 16 + local;
        bool valid = slot < n;
        int node = valid ? g_perm[(n - 1) - slot] : 0;   // descending degree

        int s = 0, deg = 0;
        if (valid) { s = g_rowptr[node]; deg = g_rowptr[node + 1] - s; }
        int cached = min(deg, CAP);

        // ---- fill: gather cached neighbor z rows, src index prefetched ----
        {
            int e = 0;
            int src = (e < cached) ? g_colsrc[s + e] : 0;
            for (; e < cached; e++) {
                int nsrc = (e + 1 < cached) ? g_colsrc[s + e + 1] : 0;
                const uint2* gz = (const uint2*)(zh_in + (size_t)src * D) + cap * 3;
                uint2 d0 = gz[0], d1 = gz[1], d2 = gz[2];
                char* base = wslab + e * 768 + lane * 8;
                *(uint2*)(base)       = d0;
                *(uint2*)(base + 256) = d1;
                *(uint2*)(base + 512) = d2;
                src = nsrc;
            }
        }

        // ---- z_self (fp32); c init = z ----
        float z[12], c[12];
        if (valid) {
            const float4* zb = (const float4*)(z32_in + (size_t)node * D + cap * FAC);
            float4 a0 = zb[0], a1 = zb[1], a2 = zb[2];
            z[0] = a0.x; z[1] = a0.y; z[2]  = a0.z; z[3]  = a0.w;
            z[4] = a1.x; z[5] = a1.y; z[6]  = a1.z; z[7]  = a1.w;
            z[8] = a2.x; z[9] = a2.y; z[10] = a2.z; z[11] = a2.w;
#pragma unroll
            for (int i = 0; i < 12; i++) c[i] = z[i];
        }
        __syncwarp();

        // ---- 6 routing iterations from smem / registers ----
        for (int it = 0; it < 6; it++) {
            float acc[12];
#pragma unroll
            for (int i = 0; i < 12; i++) acc[i] = 0.f;

            int e = 0;
            // 4-edge unrolled: four independent chains in flight
            for (; e + 3 < cached; e += 4) {
                const char* p0 = wslab + e * 768 + lane * 8;
                float f0[12], f1[12], f2[12], f3[12];
                ld_entry(p0,        f0);
                ld_entry(p0 + 768,  f1);
                ld_entry(p0 + 1536, f2);
                ld_entry(p0 + 2304, f3);
                float ex0 = __expf(dot12(f0, c));
                float ex1 = __expf(dot12(f1, c));
                float ex2 = __expf(dot12(f2, c));
                float ex3 = __expf(dot12(f3, c));
                float s0 = gsum8(ex0, mask);
                float s1 = gsum8(ex1, mask);
                float s2 = gsum8(ex2, mask);
                float s3 = gsum8(ex3, mask);
                float p0_ = __fdividef(ex0, s0);
                float p1_ = __fdividef(ex1, s1);
                float p2_ = __fdividef(ex2, s2);
                float p3_ = __fdividef(ex3, s3);
#pragma unroll
                for (int i = 0; i < 12; i++)
                    acc[i] += p0_ * f0[i] + p1_ * f1[i] + p2_ * f2[i] + p3_ * f3[i];
            }
            // 2-edge remainder
            for (; e + 1 < cached; e += 2) {
                const char* p0 = wslab + e * 768 + lane * 8;
                float f0[12], f1[12];
                ld_entry(p0,       f0);
                ld_entry(p0 + 768, f1);
                float ex0 = __expf(dot12(f0, c));
                float ex1 = __expf(dot12(f1, c));
                float s0 = gsum8(ex0, mask);
                float s1 = gsum8(ex1, mask);
                float p0_ = __fdividef(ex0, s0);
                float p1_ = __fdividef(ex1, s1);
#pragma unroll
                for (int i = 0; i < 12; i++) acc[i] += p0_ * f0[i] + p1_ * f1[i];
            }
            if (e < cached) {
                const char* p0 = wslab + e * 768 + lane * 8;
                float f0[12];
                ld_entry(p0, f0);
                float ex = __expf(dot12(f0, c));
                float sm_ = gsum8(ex, mask);
                float p = __fdividef(ex, sm_);
#pragma unroll
                for (int i = 0; i < 12; i++) acc[i] += p * f0[i];
            }
            // overflow edges streamed from L2, software-pipelined
            {
                int e2 = cached;
                uint2 P0, P1, P2;
                if (e2 < deg) {
                    const uint2* gz = (const uint2*)(zh_in + (size_t)g_colsrc[s + e2] * D + cap * FAC);
                    P0 = gz[0]; P1 = gz[1]; P2 = gz[2];
                }
                for (; e2 < deg; e2++) {
                    uint2 A0 = P0, A1 = P1, A2 = P2;
                    if (e2 + 1 < deg) {
                        const uint2* gz = (const uint2*)(zh_in + (size_t)g_colsrc[s + e2 + 1] * D + cap * FAC);
                        P0 = gz[0]; P1 = gz[1]; P2 = gz[2];
                    }
                    float fA[12];
                    cvt12(A0, A1, A2, fA);
                    float ex = __expf(dot12(fA, c));
                    float sm_ = gsum8(ex, mask);
                    float p = __fdividef(ex, sm_);
#pragma unroll
                    for (int i = 0; i < 12; i++) acc[i] += p * fA[i];
                }
            }

            float v[12];
            float ss = 0.f;
#pragma unroll
            for (int i = 0; i < 12; i++) { v[i] = z[i] + acc[i]; ss += v[i] * v[i]; }
            float rn = rsqrtf(ss + 1e-12f);
#pragma unroll
            for (int i = 0; i < 12; i++) c[i] = v[i] * rn;
        }

        if (valid) {
#pragma unroll
            for (int i = 0; i < 12; i++) c[i] = fmaxf(c[i], 0.f);  // relu
            if (mode == 0) {
                float ss = 0.f;
#pragma unroll
                for (int i = 0; i < 12; i++) ss += c[i] * c[i];
                float rn = rsqrtf(ss + 1e-12f);
#pragma unroll
                for (int i = 0; i < 12; i++) c[i] *= rn;
                float4* zp = (float4*)(z32_out + (size_t)node * D + cap * FAC);
                zp[0] = make_float4(c[0], c[1], c[2], c[3]);
                zp[1] = make_float4(c[4], c[5], c[6], c[7]);
                zp[2] = make_float4(c[8], c[9], c[10], c[11]);
                uint2* zh = (uint2*)(zh_out + (size_t)node * D + cap * FAC);
                __half2 h0 = __floats2half2_rn(c[0], c[1]);
                __half2 h1 = __floats2half2_rn(c[2], c[3]);
                __half2 h2 = __floats2half2_rn(c[4], c[5]);
                __half2 h3 = __floats2half2_rn(c[6], c[7]);
                __half2 h4 = __floats2half2_rn(c[8], c[9]);
                __half2 h5 = __floats2half2_rn(c[10], c[11]);
                zh[0] = make_uint2(*(unsigned*)&h0, *(unsigned*)&h1);
                zh[1] = make_uint2(*(unsigned*)&h2, *(unsigned*)&h3);
                zh[2] = make_uint2(*(unsigned*)&h4, *(unsigned*)&h5);
            } else {
                float4* fo = (float4*)(fout + (size_t)node * D + cap * FAC);
                fo[0] = make_float4(c[0], c[1], c[2], c[3]);
                fo[1] = make_float4(c[4], c[5], c[6], c[7]);
                fo[2] = make_float4(c[8], c[9], c[10], c[11]);
            }
        }
    }
}

// ---------------------------------------------------------------------------
extern "C" void kernel_launch(void* const* d_in, const int* in_sizes, int n_in,
                              void* d_out, int out_size) {
    const float* X     = (const float*)d_in[0];
    const int*   edges = (const int*)d_in[1];
    const float* W     = (const float*)d_in[2];
    const float* b     = (const float*)d_in[3];
    int n = in_sizes[0] / 256;   // 50000
    int m = in_sizes[1] / 2;     // 800000

    cudaFuncSetAttribute(routing_layer,
                         cudaFuncAttributeMaxDynamicSharedMemorySize, ROUTE_SMEM);

    __half* zha; cudaGetSymbolAddress((void**)&zha, g_zh_a);
    __half* zhb; cudaGetSymbolAddress((void**)&zhb, g_zh_b);
    float* z32a; cudaGetSymbolAddress((void**)&z32a, g_z32_a);
    float* z32b; cudaGetSymbolAddress((void**)&z32b, g_z32_b);

    // zero + W transpose + work-counter reset, then init layer
    zero_wt_kernel<<<(n + 255) / 256, 256>>>(W, n);
    init_gemm<<<(n + 31) / 32, 96>>>(X, b, n);

    // CSR by dst (deterministic: rows sorted by src)
    hist_kernel<<<(m + 255) / 256, 256>>>(edges, m);
    int sblocks = (n + 1023) / 1024;   // 49 <= 64
    scan1_kernel<<<sblocks, 1024>>>(n);
    scan2_kernel<<<1, 64>>>(sblocks, n);
    scan3_kernel<<<(n + 255) / 256, 256>>>(n);
    scatter_kernel<<<(m + 255) / 256, 256>>>(edges, m);
    sort_rows<<<(n + 255) / 256, 256>>>(n);

    // degree-balanced node permutation
    dhist_kernel<<<(n + 255) / 256, 256>>>(n);
    dscan_kernel<<<1, 32>>>();
    dscatter_kernel<<<(n + 255) / 256, 256>>>(n);

    // one-time prep, then 4 persistent routing layers (z double-buffered)
    prep_kernel<<<(n * KCAP + 255) / 256, 256>>>(n);
    routing_layer<<<ROUTE_GRID, 128, ROUTE_SMEM>>>(zha, z32a, zhb, z32b, nullptr, n, 0, 0);
    routing_layer<<<ROUTE_GRID, 128, ROUTE_SMEM>>>(zhb, z32b, zha, z32a, nullptr, n, 0, 1);
    routing_layer<<<ROUTE_GRID, 128, ROUTE_SMEM>>>(zha, z32a, zhb, z32b, nullptr, n, 0, 2);
    routing_layer<<<ROUTE_GRID, 128, ROUTE_SMEM>>>(zhb, z32b, nullptr, nullptr, (float*)d_out, n, 1, 3);
}

// round 11
// speedup vs baseline: 2.1404x; 1.0995x over previous
#include <cuda_runtime.h>
#include <cuda_fp16.h>

// Problem constants (fixed shapes)
#define N_MAX 50000
#define M_MAX 800000
#define D 96          // K*FAC
#define KCAP 8
#define FAC 12

#define CAP 18                        // cached neighbors per node in smem (fp16)
#define WSLAB (CAP * 768)             // per-warp slab: CAP entries x 768B
#define ROUTE_SMEM (4 * WSLAB)        // 55296 B per 128-thread block -> 4 blocks/SM
#define ROUTE_GRID 592                // 148 SMs x 4 resident blocks: one wave

typedef unsigned long long u64;

// Static scratch (no allocations allowed)
__device__ __half g_zh_a[N_MAX * D];   // fp16 z double-buffer A (gather source)
__device__ __half g_zh_b[N_MAX * D];   // fp16 z double-buffer B
__device__ float  g_z32_a[N_MAX * D];  // fp32 z double-buffer A (self-term)
__device__ float  g_z32_b[N_MAX * D];  // fp32 z double-buffer B
__device__ float  g_wt[D * 256];       // W transposed to [out=96][in=256]
__device__ int    g_deg[N_MAX];
__device__ int    g_rowptr[N_MAX + 1];
__device__ int    g_cursor[N_MAX];
__device__ int    g_colsrc[M_MAX];
__device__ int    g_bsum[64];
__device__ int    g_boff[64];
__device__ int    g_dhist[64];
__device__ int    g_dcur[64];
__device__ int    g_perm[N_MAX];
__device__ int    g_work[4];           // per-layer work-stealing counters

// ---------------- packed f32x2 helpers (init GEMM only) --------------------
__device__ __forceinline__ u64 pk2(float lo, float hi) {
    u64 r; asm("mov.b64 %0,{%1,%2};" : "=l"(r) : "f"(lo), "f"(hi)); return r;
}
__device__ __forceinline__ float2 upk2(u64 v) {
    float2 f; asm("mov.b64 {%0,%1},%2;" : "=f"(f.x), "=f"(f.y) : "l"(v)); return f;
}
__device__ __forceinline__ u64 fma2_(u64 a, u64 b, u64 c) {
    u64 d; asm("fma.rn.f32x2 %0,%1,%2,%3;" : "=l"(d) : "l"(a), "l"(b), "l"(c)); return d;
}

// 8-lane group sum (3-shuffle butterfly; fp32 redux unsupported on sm_103)
__device__ __forceinline__ float gsum8(float v, unsigned mask) {
    v += __shfl_xor_sync(mask, v, 1);
    v += __shfl_xor_sync(mask, v, 2);
    v += __shfl_xor_sync(mask, v, 4);
    return v;
}

// ---------------------------------------------------------------------------
// zero + W transpose fused; also resets work-stealing counters each replay.
__global__ void zero_wt_kernel(const float* __restrict__ W, int n) {
    int i = blockIdx.x * blockDim.x + threadIdx.x;
    if (i < n) g_deg[i] = 0;
    if (i < 64) g_dhist[i] = 0;
    if (i < 4) g_work[i] = 0;
    if (i < D * 256) {
        int o = i >> 8, c = i & 255;
        int k = o / FAC, oo = o % FAC;
        g_wt[i] = W[k * (256 * FAC) + c * FAC + oo];
    }
}

// ---------------------------------------------------------------------------
// Init layer fused with prep: Z = relu(X.Wt + b) staged in smem, then
// z = l2norm(Z) written to z32_a (fp32) + zh_a (fp16). f32x2 FMA mainloop.
__global__ void __launch_bounds__(96) init_gemm(const float* __restrict__ X,
                                                const float* __restrict__ bv, int n) {
    __shared__ float xs[32][256];
    __shared__ float os[32][96];
    int t = threadIdx.x;
    int nb = blockIdx.x * 32;
    for (int j = t; j < 32 * 256; j += 96) {
        int q = j >> 8;
        xs[q][j & 255] = (nb + q < n) ? X[nb * 256 + j] : 0.f;
    }
    __syncthreads();

    u64 acc[32];
#pragma unroll
    for (int q = 0; q < 32; q++) acc[q] = 0ull;

    const float4* wrow = (const float4*)(g_wt + t * 256);
#pragma unroll 2
    for (int i4 = 0; i4 < 64; i4++) {
        float4 w = wrow[i4];
        u64 w01 = pk2(w.x, w.y);
        u64 w23 = pk2(w.z, w.w);
#pragma unroll
        for (int q = 0; q < 32; q++) {
            float4 xv = *(const float4*)&xs[q][i4 * 4];
            acc[q] = fma2_(w01, pk2(xv.x, xv.y), acc[q]);
            acc[q] = fma2_(w23, pk2(xv.z, xv.w), acc[q]);
        }
    }
    float bb = bv[t];
#pragma unroll
    for (int q = 0; q < 32; q++) {
        float2 h = upk2(acc[q]);
        os[q][t] = fmaxf(h.x + h.y + bb, 0.f);   // relu(Z)
    }
    __syncthreads();

    // prep: per (node, capsule) l2norm -> z32_a + zh_a
    for (int idx = t; idx < 32 * KCAP; idx += 96) {
        int q = idx >> 3, cp = idx & 7;
        if (nb + q >= n) continue;
        const float* r = &os[q][cp * FAC];
        float v[12];
        float s = 0.f;
#pragma unroll
        for (int i = 0; i < 12; i++) { v[i] = r[i]; s += v[i] * v[i]; }
        float rn = rsqrtf(s + 1e-12f);
#pragma unroll
        for (int i = 0; i < 12; i++) v[i] *= rn;
        int gi = ((nb + q) * KCAP + cp) * FAC;
        float4* zp = (float4*)(g_z32_a + gi);
        zp[0] = make_float4(v[0], v[1], v[2], v[3]);
        zp[1] = make_float4(v[4], v[5], v[6], v[7]);
        zp[2] = make_float4(v[8], v[9], v[10], v[11]);
        uint2* zh = (uint2*)(g_zh_a + gi);
        __half2 h0 = __floats2half2_rn(v[0], v[1]);
        __half2 h1 = __floats2half2_rn(v[2], v[3]);
        __half2 h2 = __floats2half2_rn(v[4], v[5]);
        __half2 h3 = __floats2half2_rn(v[6], v[7]);
        __half2 h4 = __floats2half2_rn(v[8], v[9]);
        __half2 h5 = __floats2half2_rn(v[10], v[11]);
        zh[0] = make_uint2(*(unsigned*)&h0, *(unsigned*)&h1);
        zh[1] = make_uint2(*(unsigned*)&h2, *(unsigned*)&h3);
        zh[2] = make_uint2(*(unsigned*)&h4, *(unsigned*)&h5);
    }
}

// ---------------------------------------------------------------------------
// CSR build: hist -> 3-phase hierarchical scan (with perm stages fused)
__global__ void hist_kernel(const int* __restrict__ edges, int m) {
    int e = blockIdx.x * blockDim.x + threadIdx.x;
    if (e < m) atomicAdd(&g_deg[edges[m + e]], 1);
}

// phase 1: block-local exclusive scan of degrees + degree histogram (fused)
__global__ void scan1_kernel(int n) {
    __shared__ int wsum[32];
    __shared__ int h[64];
    int t = threadIdx.x, lane = t & 31, wid = t >> 5;
    if (t < 64) h[t] = 0;
    int idx = blockIdx.x * 1024 + t;
    int v = (idx < n) ? g_deg[idx] : 0;
    int x = v;
#pragma unroll
    for (int off = 1; off < 32; off <<= 1) {
        int y = __shfl_up_sync(0xffffffffu, x, off);
        if (lane >= off) x += y;
    }
    if (lane == 31) wsum[wid] = x;
    __syncthreads();
    if (wid == 0) {
        int w = wsum[lane];
#pragma unroll
        for (int off = 1; off < 32; off <<= 1) {
            int y = __shfl_up_sync(0xffffffffu, w, off);
            if (lane >= off) w += y;
        }
        wsum[lane] = w;
    }
    if (idx < n) atomicAdd(&h[min(v, 63)], 1);
    __syncthreads();
    int pre = (wid > 0) ? wsum[wid - 1] : 0;
    if (idx < n) g_rowptr[idx] = pre + x - v;   // block-local exclusive
    if (t == 1023) g_bsum[blockIdx.x] = pre + x;
    if (t < 64 && h[t]) atomicAdd(&g_dhist[t], h[t]);
}

// phase 2: scan of block totals + degree-bucket scan (fused)
__global__ void scan2_kernel(int nblocks, int n) {
    int t = threadIdx.x;  // 64 threads
    int v = (t < nblocks) ? g_bsum[t] : 0;
    int x = v;
    int lane = t & 31, wid = t >> 5;
    __shared__ int ws[2];
#pragma unroll
    for (int off = 1; off < 32; off <<= 1) {
        int y = __shfl_up_sync(0xffffffffu, x, off);
        if (lane >= off) x += y;
    }
    if (lane == 31) ws[wid] = x;
    __syncthreads();
    int add = (wid == 1) ? ws[0] : 0;
    g_boff[t] = add + x - v;
    if (t == 63) g_rowptr[n] = add + x;
    if (t == 0) {
        int run = 0;
        for (int i = 0; i < 64; i++) { g_dcur[i] = run; run += g_dhist[i]; }
    }
}

// phase 3: finalize rowptr/cursor + degree-bucket scatter -> perm (fused)
__global__ void scan3_kernel(int n) {
    int idx = blockIdx.x * blockDim.x + threadIdx.x;
    if (idx < n) {
        int r = g_rowptr[idx] + g_boff[idx >> 10];
        g_rowptr[idx] = r;
        g_cursor[idx] = r;
        int pos = atomicAdd(&g_dcur[min(g_deg[idx], 63)], 1);
        g_perm[pos] = idx;
    }
}

__global__ void scatter_kernel(const int* __restrict__ edges, int m) {
    int e = blockIdx.x * blockDim.x + threadIdx.x;
    if (e < m) {
        int d = edges[m + e];
        int pos = atomicAdd(&g_cursor[d], 1);
        g_colsrc[pos] = edges[e];
    }
}

// Sort each row's src list: deterministic accumulation order.
__global__ void sort_rows(int n) {
    int node = blockIdx.x * blockDim.x + threadIdx.x;
    if (node >= n) return;
    int s = g_rowptr[node], e = g_rowptr[node + 1];
    for (int i = s + 1; i < e; i++) {
        int v = g_colsrc[i];
        int j = i - 1;
        while (j >= s && g_colsrc[j] > v) { g_colsrc[j + 1] = g_colsrc[j]; j--; }
        g_colsrc[j + 1] = v;
    }
}

// ---------------------------------------------------------------------------
__device__ __forceinline__ void cvt12_ab(uint4 a, uint2 b, float* f) {
    float2 t;
    t = __half22float2(*(__half2*)&a.x); f[0] = t.x;  f[1] = t.y;
    t = __half22float2(*(__half2*)&a.y); f[2] = t.x;  f[3] = t.y;
    t = __half22float2(*(__half2*)&a.z); f[4] = t.x;  f[5] = t.y;
    t = __half22float2(*(__half2*)&a.w); f[6] = t.x;  f[7] = t.y;
    t = __half22float2(*(__half2*)&b.x); f[8] = t.x;  f[9] = t.y;
    t = __half22float2(*(__half2*)&b.y); f[10] = t.x; f[11] = t.y;
}

// load one smem entry: 16B chunk + 8B chunk (2 LDS, conflict-free)
__device__ __forceinline__ void ld_entry(const char* ebase, int lane, float* f) {
    uint4 a = *(const uint4*)(ebase + lane * 16);
    uint2 b = *(const uint2*)(ebase + 512 + lane * 8);
    cvt12_ab(a, b, f);
}

__device__ __forceinline__ float dot12(const float* f, const float* c) {
    float a0 = f[0]*c[0] + f[1]*c[1] + f[2]*c[2] + f[3]*c[3];
    float a1 = f[4]*c[4] + f[5]*c[5] + f[6]*c[6] + f[7]*c[7];
    float a2 = f[8]*c[8] + f[9]*c[9] + f[10]*c[10] + f[11]*c[11];
    return a0 + a1 + a2;
}

// Persistent work-stealing routing layer (single wave of 592 blocks).
// Entry layout: [16B x 32 lanes][8B x 32 lanes] per edge (768 B), 2 LDS/entry.
// 4-edge unrolled inner loop; pipelined overflow; descending-degree chunks.
// mode 0: write z_next = l2norm(relu(c)); mode 1: write relu(c) to fout.
__global__ void __launch_bounds__(128, 4)
routing_layer(const __half* __restrict__ zh_in, const float* __restrict__ z32_in,
              __half* __restrict__ zh_out, float* __restrict__ z32_out,
              float* __restrict__ fout, int n, int mode, int widx) {
    extern __shared__ char sm[];
    __shared__ int chunk_s;
    int lane = threadIdx.x & 31;
    int warp = threadIdx.x >> 5;
    int group = lane >> 3;
    int cap = lane & 7;
    unsigned mask = 0xFFu << (group << 3);
    int local = warp * 4 + group;
    int nchunks = (n + 15) / 16;

    char* wslab = sm + warp * WSLAB;

    while (true) {
        if (threadIdx.x == 0) chunk_s = atomicAdd(&g_work[widx], 1);
        __syncthreads();
        int chunk = chunk_s;
        __syncthreads();   // chunk_s safe to overwrite next round
        if (chunk >= nchunks) break;

        int slot = chunk * 16 + local;
        bool valid = slot < n;
        int node = valid ? g_perm[(n - 1) - slot] : 0;   // descending degree

        int s = 0, deg = 0;
        if (valid) { s = g_rowptr[node]; deg = g_rowptr[node + 1] - s; }
        int cached = min(deg, CAP);

        // ---- fill: gather cached neighbor z rows, src index prefetched ----
        {
            int e = 0;
            int src = (e < cached) ? g_colsrc[s + e] : 0;
            for (; e < cached; e++) {
                int nsrc = (e + 1 < cached) ? g_colsrc[s + e + 1] : 0;
                const uint2* gz = (const uint2*)(zh_in + (size_t)src * D) + cap * 3;
                uint2 d0 = gz[0], d1 = gz[1], d2 = gz[2];
                char* ebase = wslab + e * 768;
                *(uint4*)(ebase + lane * 16) = make_uint4(d0.x, d0.y, d1.x, d1.y);
                *(uint2*)(ebase + 512 + lane * 8) = d2;
                src = nsrc;
            }
        }

        // ---- z_self (fp32); c init = z ----
        float z[12], c[12];
        if (valid) {
            const float4* zb = (const float4*)(z32_in + (size_t)node * D + cap * FAC);
            float4 a0 = zb[0], a1 = zb[1], a2 = zb[2];
            z[0] = a0.x; z[1] = a0.y; z[2]  = a0.z; z[3]  = a0.w;
            z[4] = a1.x; z[5] = a1.y; z[6]  = a1.z; z[7]  = a1.w;
            z[8] = a2.x; z[9] = a2.y; z[10] = a2.z; z[11] = a2.w;
#pragma unroll
            for (int i = 0; i < 12; i++) c[i] = z[i];
        }
        __syncwarp();

        // ---- 6 routing iterations from smem / registers ----
        for (int it = 0; it < 6; it++) {
            float acc[12];
#pragma unroll
            for (int i = 0; i < 12; i++) acc[i] = 0.f;

            int e = 0;
            // 4-edge unrolled: four independent chains in flight
            for (; e + 3 < cached; e += 4) {
                const char* p0 = wslab + e * 768;
                float f0[12], f1[12], f2[12], f3[12];
                ld_entry(p0,        lane, f0);
                ld_entry(p0 + 768,  lane, f1);
                ld_entry(p0 + 1536, lane, f2);
                ld_entry(p0 + 2304, lane, f3);
                float ex0 = __expf(dot12(f0, c));
                float ex1 = __expf(dot12(f1, c));
                float ex2 = __expf(dot12(f2, c));
                float ex3 = __expf(dot12(f3, c));
                float s0 = gsum8(ex0, mask);
                float s1 = gsum8(ex1, mask);
                float s2 = gsum8(ex2, mask);
                float s3 = gsum8(ex3, mask);
                float p0_ = __fdividef(ex0, s0);
                float p1_ = __fdividef(ex1, s1);
                float p2_ = __fdividef(ex2, s2);
                float p3_ = __fdividef(ex3, s3);
#pragma unroll
                for (int i = 0; i < 12; i++)
                    acc[i] += p0_ * f0[i] + p1_ * f1[i] + p2_ * f2[i] + p3_ * f3[i];
            }
            // 2-edge remainder
            for (; e + 1 < cached; e += 2) {
                const char* p0 = wslab + e * 768;
                float f0[12], f1[12];
                ld_entry(p0,       lane, f0);
                ld_entry(p0 + 768, lane, f1);
                float ex0 = __expf(dot12(f0, c));
                float ex1 = __expf(dot12(f1, c));
                float s0 = gsum8(ex0, mask);
                float s1 = gsum8(ex1, mask);
                float p0_ = __fdividef(ex0, s0);
                float p1_ = __fdividef(ex1, s1);
#pragma unroll
                for (int i = 0; i < 12; i++) acc[i] += p0_ * f0[i] + p1_ * f1[i];
            }
            if (e < cached) {
                const char* p0 = wslab + e * 768;
                float f0[12];
                ld_entry(p0, lane, f0);
                float ex = __expf(dot12(f0, c));
                float sm_ = gsum8(ex, mask);
                float p = __fdividef(ex, sm_);
#pragma unroll
                for (int i = 0; i < 12; i++) acc[i] += p * f0[i];
            }
            // overflow edges streamed from L2, software-pipelined
            {
                int e2 = cached;
                uint2 P0, P1, P2;
                if (e2 < deg) {
                    const uint2* gz = (const uint2*)(zh_in + (size_t)g_colsrc[s + e2] * D + cap * FAC);
                    P0 = gz[0]; P1 = gz[1]; P2 = gz[2];
                }
                for (; e2 < deg; e2++) {
                    uint2 A0 = P0, A1 = P1, A2 = P2;
                    if (e2 + 1 < deg) {
                        const uint2* gz = (const uint2*)(zh_in + (size_t)g_colsrc[s + e2 + 1] * D + cap * FAC);
                        P0 = gz[0]; P1 = gz[1]; P2 = gz[2];
                    }
                    float fA[12];
                    cvt12_ab(make_uint4(A0.x, A0.y, A1.x, A1.y), A2, fA);
                    float ex = __expf(dot12(fA, c));
                    float sm_ = gsum8(ex, mask);
                    float p = __fdividef(ex, sm_);
#pragma unroll
                    for (int i = 0; i < 12; i++) acc[i] += p * fA[i];
                }
            }

            float v[12];
            float ss = 0.f;
#pragma unroll
            for (int i = 0; i < 12; i++) { v[i] = z[i] + acc[i]; ss += v[i] * v[i]; }
            float rn = rsqrtf(ss + 1e-12f);
#pragma unroll
            for (int i = 0; i < 12; i++) c[i] = v[i] * rn;
        }

        if (valid) {
#pragma unroll
            for (int i = 0; i < 12; i++) c[i] = fmaxf(c[i], 0.f);  // relu
            if (mode == 0) {
                float ss = 0.f;
#pragma unroll
                for (int i = 0; i < 12; i++) ss += c[i] * c[i];
                float rn = rsqrtf(ss + 1e-12f);
#pragma unroll
                for (int i = 0; i < 12; i++) c[i] *= rn;
                float4* zp = (float4*)(z32_out + (size_t)node * D + cap * FAC);
                zp[0] = make_float4(c[0], c[1], c[2], c[3]);
                zp[1] = make_float4(c[4], c[5], c[6], c[7]);
                zp[2] = make_float4(c[8], c[9], c[10], c[11]);
                uint2* zh = (uint2*)(zh_out + (size_t)node * D + cap * FAC);
                __half2 h0 = __floats2half2_rn(c[0], c[1]);
                __half2 h1 = __floats2half2_rn(c[2], c[3]);
                __half2 h2 = __floats2half2_rn(c[4], c[5]);
                __half2 h3 = __floats2half2_rn(c[6], c[7]);
                __half2 h4 = __floats2half2_rn(c[8], c[9]);
                __half2 h5 = __floats2half2_rn(c[10], c[11]);
                zh[0] = make_uint2(*(unsigned*)&h0, *(unsigned*)&h1);
                zh[1] = make_uint2(*(unsigned*)&h2, *(unsigned*)&h3);
                zh[2] = make_uint2(*(unsigned*)&h4, *(unsigned*)&h5);
            } else {
                float4* fo = (float4*)(fout + (size_t)node * D + cap * FAC);
                fo[0] = make_float4(c[0], c[1], c[2], c[3]);
                fo[1] = make_float4(c[4], c[5], c[6], c[7]);
                fo[2] = make_float4(c[8], c[9], c[10], c[11]);
            }
        }
    }
}

// ---------------------------------------------------------------------------
extern "C" void kernel_launch(void* const* d_in, const int* in_sizes, int n_in,
                              void* d_out, int out_size) {
    const float* X     = (const float*)d_in[0];
    const int*   edges = (const int*)d_in[1];
    const float* W     = (const float*)d_in[2];
    const float* b     = (const float*)d_in[3];
    int n = in_sizes[0] / 256;   // 50000
    int m = in_sizes[1] / 2;     // 800000

    cudaFuncSetAttribute(routing_layer,
                         cudaFuncAttributeMaxDynamicSharedMemorySize, ROUTE_SMEM);

    __half* zha; cudaGetSymbolAddress((void**)&zha, g_zh_a);
    __half* zhb; cudaGetSymbolAddress((void**)&zhb, g_zh_b);
    float* z32a; cudaGetSymbolAddress((void**)&z32a, g_z32_a);
    float* z32b; cudaGetSymbolAddress((void**)&z32b, g_z32_b);

    // zero + W transpose + work-counter reset, then init+prep fused
    zero_wt_kernel<<<(n + 255) / 256, 256>>>(W, n);
    init_gemm<<<(n + 31) / 32, 96>>>(X, b, n);

    // CSR by dst (deterministic: rows sorted by src); perm fused into scans
    hist_kernel<<<(m + 255) / 256, 256>>>(edges, m);
    int sblocks = (n + 1023) / 1024;   // 49 <= 64
    scan1_kernel<<<sblocks, 1024>>>(n);
    scan2_kernel<<<1, 64>>>(sblocks, n);
    scan3_kernel<<<(n + 255) / 256, 256>>>(n);
    scatter_kernel<<<(m + 255) / 256, 256>>>(edges, m);
    sort_rows<<<(n + 255) / 256, 256>>>(n);

    // 4 persistent routing layers (z double-buffered)
    routing_layer<<<ROUTE_GRID, 128, ROUTE_SMEM>>>(zha, z32a, zhb, z32b, nullptr, n, 0, 0);
    routing_layer<<<ROUTE_GRID, 128, ROUTE_SMEM>>>(zhb, z32b, zha, z32a, nullptr, n, 0, 1);
    routing_layer<<<ROUTE_GRID, 128, ROUTE_SMEM>>>(zha, z32a, zhb, z32b, nullptr, n, 0, 2);
    routing_layer<<<ROUTE_GRID, 128, ROUTE_SMEM>>>(zhb, z32b, nullptr, nullptr, (float*)d_out, n, 1, 3);
}